// round 13
// baseline (speedup 1.0000x reference)
#include <cuda_runtime.h>
#include <cuda_bf16.h>
#include <cuda_fp16.h>
#include <math.h>
#include <cstdint>

typedef unsigned int u32;
typedef unsigned short u16;
typedef unsigned long long u64;

// Problem constants
#define Bn 4
#define Cc 512
#define Hh 56
#define Ww 56
#define Gg 16
#define Pp 9
#define GC 32
#define HW 3136          // 56*56
#define Mtot 12544       // B*H*W
#define Noff 288         // G*P*2
#define Nmsk 144         // G*P
#define Ncat 432         // Noff+Nmsk
#define NPAD 512         // Ncat padded to 128 multiple

// ---------------- scratch (device globals; no allocation allowed) ----------
__device__ float  g_xh[Mtot * Cc];        // NHWC input fp32 (for depthwise)
__device__ float  g_xa[Mtot * Cc];        // tf32-rounded NHWC (GEMM1 A)
__device__ __half g_xph[Mtot * Cc];       // input_proj output fp16 (dcn only)
__device__ float  g_x1[Mtot * Cc];        // dw+LN+GELU, tf32-rounded (GEMM2 A)
__device__ float  g_om[Mtot * Ncat];      // [offset|mask logits]
__device__ float  g_ys[Mtot * Cc];        // DCN output, tf32-rounded (GEMM3 A)
__device__ float  g_winT[Cc * Cc];        // w_in^T tf32-rounded: [n][k]
__device__ float  g_wcatT[NPAD * Cc];     // concat weight^T tf32-rounded: [n][k]
__device__ float  g_woutT[Cc * Cc];       // w_out^T tf32-rounded: [n][k]
__device__ float  g_bcat[NPAD];

// ---------------- helpers ---------------------------------------------------
__device__ __forceinline__ float tf32r(float v) {
    u32 r;
    asm("cvt.rna.tf32.f32 %0, %1;" : "=r"(r) : "f"(v));
    return __uint_as_float(r);
}
__device__ __forceinline__ void ldmA4(u32* r, u32 addr) {
    asm volatile("ldmatrix.sync.aligned.m8n8.x4.shared.b16 {%0,%1,%2,%3}, [%4];\n"
                 : "=r"(r[0]), "=r"(r[1]), "=r"(r[2]), "=r"(r[3]) : "r"(addr));
}
__device__ __forceinline__ void ldmB4(u32* r, u32 addr) {
    asm volatile("ldmatrix.sync.aligned.m8n8.x4.shared.b16 {%0,%1,%2,%3}, [%4];\n"
                 : "=r"(r[0]), "=r"(r[1]), "=r"(r[2]), "=r"(r[3]) : "r"(addr));
}
__device__ __forceinline__ void mma_tf32(float* c, const u32* a, const u32* b) {
    asm volatile("mma.sync.aligned.m16n8k8.row.col.f32.tf32.tf32.f32 "
                 "{%0,%1,%2,%3}, {%4,%5,%6,%7}, {%8,%9}, {%0,%1,%2,%3};\n"
                 : "+f"(c[0]), "+f"(c[1]), "+f"(c[2]), "+f"(c[3])
                 : "r"(a[0]), "r"(a[1]), "r"(a[2]), "r"(a[3]), "r"(b[0]), "r"(b[1]));
}
__device__ __forceinline__ void cpa16(u32 dst, const void* src) {
    asm volatile("cp.async.cg.shared.global [%0], [%1], 16;\n" :: "r"(dst), "l"(src));
}
__device__ __forceinline__ void cpcommit() { asm volatile("cp.async.commit_group;\n"); }
__device__ __forceinline__ void cpwait0() { asm volatile("cp.async.wait_group 0;\n"); }
__device__ __forceinline__ void cpwait1() { asm volatile("cp.async.wait_group 1;\n"); }

// ---------------- fused weight prep -----------------------------------------
__global__ __launch_bounds__(256)
void prep_weights(const float* __restrict__ w_in, const float* __restrict__ w_out,
                  const float* __restrict__ w_off, const float* __restrict__ b_off,
                  const float* __restrict__ w_mask, const float* __restrict__ b_mask) {
    const int seg = blockIdx.x >> 10;
    const int i = ((blockIdx.x & 1023) << 8) + threadIdx.x;
    if (seg == 0) {
        const int k = i >> 9;
        const int n = i & 511;
        g_winT[n * Cc + k] = tf32r(w_in[i]);
    } else if (seg == 1) {
        const int k = i >> 9;
        const int n = i & 511;
        g_woutT[n * Cc + k] = tf32r(w_out[i]);
    } else {
        const int n = i >> 9;
        const int k = i & 511;
        float v = 0.f;
        if (n < Noff) v = w_off[k * Noff + n];
        else if (n < Ncat) v = w_mask[k * Nmsk + (n - Noff)];
        g_wcatT[i] = tf32r(v);
        if (i < NPAD)
            g_bcat[i] = (i < Noff) ? b_off[i] : (i < Ncat ? b_mask[i - Noff] : 0.f);
    }
}

// ---------------- NCHW -> NHWC transpose (+ tf32 copy) ----------------------
__global__ __launch_bounds__(256)
void nchw_to_nhwc(const float* __restrict__ x) {
    __shared__ float tile[32][33];
    const int bb = blockIdx.z;
    const int hw0 = blockIdx.x * 32;
    const int c0 = blockIdx.y * 32;
    const int tx = threadIdx.x;
    const int ty = threadIdx.y;
    const float* xb = x + (size_t)bb * Cc * HW;
    #pragma unroll
    for (int i = 0; i < 32; i += 8)
        tile[ty + i][tx] = xb[(size_t)(c0 + ty + i) * HW + hw0 + tx];
    __syncthreads();
    #pragma unroll
    for (int i = 0; i < 32; i += 8) {
        const size_t idx = ((size_t)bb * HW + hw0 + ty + i) * Cc + c0 + tx;
        const float v = tile[tx][ty + i];
        g_xh[idx] = v;
        g_xa[idx] = tf32r(v);
    }
}

// ================= tf32 GEMM: BM=128 BN=128 BK=32, 3-stage ==================
#define TF_STG 32768
#define TF_DSMEM (3 * TF_STG)

__device__ __forceinline__ void tf_fill(const float* __restrict__ A,
                                        const float* __restrict__ B,
                                        int bm, int bn, int kt, u32 stg) {
    const int t = threadIdx.x;
    const int row = t >> 1;
    const int cb = (t & 1) * 4;
    const size_t ka = (size_t)(bm + row) * Cc + kt * 32;
    const size_t kb = (size_t)(bn + row) * Cc + kt * 32;
    #pragma unroll
    for (int i = 0; i < 4; i++) {
        const int c = cb + i;
        const u32 d = (u32)(row * 128 + ((c ^ (row & 7)) << 4));
        cpa16(stg + d,         (const void*)(A + ka + c * 4));
        cpa16(stg + 16384 + d, (const void*)(B + kb + c * 4));
    }
    cpcommit();
}

__device__ __forceinline__ void tf_compute(u32 stg, int wm, int wn, int lane,
                                           float acc[4][4][4]) {
    const u32 stgB = stg + 16384;
    const int arow7 = lane & 7;
    const int arow8 = ((lane >> 3) & 1) * 8;
    const int achk = lane >> 4;
    // B x4 mapping: lanes 0-7 -> (nf, klo), 8-15 -> (nf, khi),
    //               16-23 -> (nf+1, klo), 24-31 -> (nf+1, khi)
    const int brow8 = (lane >> 4) * 8;        // +8 rows for second nf
    const int bchk = (lane >> 3) & 1;         // k-chunk within pair
    #pragma unroll
    for (int ks = 0; ks < 4; ks++) {
        u32 a[4][4];
        #pragma unroll
        for (int mf = 0; mf < 4; mf++) {
            const int row = wm + mf * 16 + arow7 + arow8;
            const int ch = 2 * ks + achk;
            ldmA4(a[mf], stg + (u32)(row * 128 + ((ch ^ (row & 7)) << 4)));
        }
        u32 b4[2][4];   // b4[j] = {nf=2j:b0,b1, nf=2j+1:b0,b1}
        #pragma unroll
        for (int j = 0; j < 2; j++) {
            const int row = wn + (2 * j) * 8 + brow8 + arow7;
            const int ch = 2 * ks + bchk;
            ldmB4(b4[j], stgB + (u32)(row * 128 + ((ch ^ (row & 7)) << 4)));
        }
        #pragma unroll
        for (int mf = 0; mf < 4; mf++) {
            #pragma unroll
            for (int j = 0; j < 2; j++) {
                mma_tf32(acc[mf][2 * j + 0], a[mf], &b4[j][0]);
                mma_tf32(acc[mf][2 * j + 1], a[mf], &b4[j][2]);
            }
        }
    }
}

__device__ __forceinline__ void tf_core(const float* __restrict__ A,
                                        const float* __restrict__ B,
                                        int bm, int bn, u32 smbase,
                                        float acc[4][4][4]) {
    const int wid = threadIdx.x >> 5;
    const int lane = threadIdx.x & 31;
    const int wm = (wid & 1) * 64;
    const int wn = (wid >> 1) * 32;
    const u32 st[3] = {smbase, smbase + TF_STG, smbase + 2 * TF_STG};
    tf_fill(A, B, bm, bn, 0, st[0]);
    tf_fill(A, B, bm, bn, 1, st[1]);
    #pragma unroll 1
    for (int kt = 0; kt < 16; kt++) {
        if (kt == 15) cpwait0(); else cpwait1();
        __syncthreads();
        if (kt + 2 < 16) {
            int s2 = kt + 2; s2 -= (s2 / 3) * 3;
            tf_fill(A, B, bm, bn, kt + 2, st[s2]);
        }
        int s = kt; s -= (s / 3) * 3;
        tf_compute(st[s], wm, wn, lane, acc);
    }
}

// ---- GEMM 1 (tf32): xp(fp16) = xa @ winT^T + b_in --------------------------
__global__ __launch_bounds__(256, 2)
void gemm_in(const float* __restrict__ bias) {
    extern __shared__ char smem[];
    const u32 smbase = (u32)__cvta_generic_to_shared(smem);
    float acc[4][4][4];
    #pragma unroll
    for (int i = 0; i < 4; i++)
        #pragma unroll
        for (int j = 0; j < 4; j++)
            #pragma unroll
            for (int q = 0; q < 4; q++) acc[i][j][q] = 0.f;
    const int bm = blockIdx.y * 128;
    const int bn = blockIdx.x * 128;
    tf_core(g_xa, g_winT, bm, bn, smbase, acc);

    const int wid = threadIdx.x >> 5;
    const int lane = threadIdx.x & 31;
    const int wm = (wid & 1) * 64;
    const int wn = (wid >> 1) * 32;
    const int r0 = lane >> 2;
    const int c0 = (lane & 3) * 2;
    #pragma unroll
    for (int mf = 0; mf < 4; mf++) {
        #pragma unroll
        for (int nf = 0; nf < 4; nf++) {
            const int col = bn + wn + nf * 8 + c0;
            #pragma unroll
            for (int half = 0; half < 2; half++) {
                const int row = bm + wm + mf * 16 + r0 + half * 8;
                const float y0 = acc[mf][nf][half * 2 + 0] + bias[col];
                const float y1 = acc[mf][nf][half * 2 + 1] + bias[col + 1];
                *(__half2*)&g_xph[(size_t)row * Cc + col] = __floats2half2_rn(y0, y1);
            }
        }
    }
}

// ---- GEMM 2 (tf32): g_om = x1 @ wcatT^T + bcat  (N=512 pad, store 432) -----
__global__ __launch_bounds__(256, 2)
void gemm_om() {
    extern __shared__ char smem[];
    const u32 smbase = (u32)__cvta_generic_to_shared(smem);
    float acc[4][4][4];
    #pragma unroll
    for (int i = 0; i < 4; i++)
        #pragma unroll
        for (int j = 0; j < 4; j++)
            #pragma unroll
            for (int q = 0; q < 4; q++) acc[i][j][q] = 0.f;
    const int bm = blockIdx.y * 128;
    const int bn = blockIdx.x * 128;
    tf_core(g_x1, g_wcatT, bm, bn, smbase, acc);

    const int wid = threadIdx.x >> 5;
    const int lane = threadIdx.x & 31;
    const int wm = (wid & 1) * 64;
    const int wn = (wid >> 1) * 32;
    const int r0 = lane >> 2;
    const int c0 = (lane & 3) * 2;
    #pragma unroll
    for (int mf = 0; mf < 4; mf++) {
        #pragma unroll
        for (int nf = 0; nf < 4; nf++) {
            const int col = bn + wn + nf * 8 + c0;
            if (col < Ncat) {
                #pragma unroll
                for (int half = 0; half < 2; half++) {
                    const int row = bm + wm + mf * 16 + r0 + half * 8;
                    float2 v;
                    v.x = acc[mf][nf][half * 2 + 0] + g_bcat[col];
                    v.y = acc[mf][nf][half * 2 + 1] + g_bcat[col + 1];
                    *(float2*)&g_om[(size_t)row * Ncat + col] = v;
                }
            }
        }
    }
}

// ---- GEMM 3 (tf32): out = SiLU(BN(ys @ woutT^T + b_out)) in NCHW -----------
__global__ __launch_bounds__(256, 2)
void gemm_out(const float* __restrict__ bias,
              const float* __restrict__ bn_g, const float* __restrict__ bn_b,
              const float* __restrict__ bn_m, const float* __restrict__ bn_v,
              float* __restrict__ out) {
    extern __shared__ char smem[];
    const u32 smbase = (u32)__cvta_generic_to_shared(smem);
    float acc[4][4][4];
    #pragma unroll
    for (int i = 0; i < 4; i++)
        #pragma unroll
        for (int j = 0; j < 4; j++)
            #pragma unroll
            for (int q = 0; q < 4; q++) acc[i][j][q] = 0.f;
    const int bm = blockIdx.y * 128;
    const int bn = blockIdx.x * 128;
    tf_core(g_ys, g_woutT, bm, bn, smbase, acc);

    const int wid = threadIdx.x >> 5;
    const int lane = threadIdx.x & 31;
    const int wm = (wid & 1) * 64;
    const int wn = (wid >> 1) * 32;
    const int r0 = lane >> 2;
    const int c0 = (lane & 3) * 2;
    #pragma unroll
    for (int mf = 0; mf < 4; mf++) {
        #pragma unroll
        for (int nf = 0; nf < 4; nf++) {
            const int col = bn + wn + nf * 8 + c0;
            const float s0 = bn_g[col] * rsqrtf(bn_v[col] + 1e-5f);
            const float s1 = bn_g[col + 1] * rsqrtf(bn_v[col + 1] + 1e-5f);
            #pragma unroll
            for (int half = 0; half < 2; half++) {
                const int row = bm + wm + mf * 16 + r0 + half * 8;
                const int bidx = row / HW;
                const int hw = row - bidx * HW;
                float y0 = acc[mf][nf][half * 2 + 0] + bias[col];
                float y1 = acc[mf][nf][half * 2 + 1] + bias[col + 1];
                y0 = (y0 - bn_m[col]) * s0 + bn_b[col];
                y1 = (y1 - bn_m[col + 1]) * s1 + bn_b[col + 1];
                out[((size_t)bidx * Cc + col) * HW + hw]     = y0 / (1.0f + expf(-y0));
                out[((size_t)bidx * Cc + col + 1) * HW + hw] = y1 / (1.0f + expf(-y1));
            }
        }
    }
}

// ------- depthwise 3x3 + LN + GELU: 8-pixel sliding window per block -------
__global__ __launch_bounds__(256)
void dw_ln_gelu(const float* __restrict__ wdw, const float* __restrict__ bdw,
                const float* __restrict__ lng, const float* __restrict__ lnb) {
    __shared__ float sA[8][8];
    __shared__ float sB[8][8];
    const int m0 = blockIdx.x * 8;
    const int b = m0 / HW;
    const int hw0 = m0 - b * HW;
    const int h = hw0 / Ww;
    const int w0 = hw0 - h * Ww;
    const int tid = threadIdx.x;
    const int wid = tid >> 5;
    const int lane = tid & 31;
    const int c = tid * 2;

    float a0[8], a1[8];
    #pragma unroll
    for (int i = 0; i < 8; i++) { a0[i] = 0.f; a1[i] = 0.f; }

    #pragma unroll
    for (int ky = 0; ky < 3; ky++) {
        const int hy = h + ky - 1;
        if ((unsigned)hy >= (unsigned)Hh) continue;
        const float2 wv0 = *(const float2*)&wdw[(ky * 3 + 0) * Cc + c];
        const float2 wv1 = *(const float2*)&wdw[(ky * 3 + 1) * Cc + c];
        const float2 wv2 = *(const float2*)&wdw[(ky * 3 + 2) * Cc + c];
        float2 rv[10];
        #pragma unroll
        for (int j = 0; j < 10; j++) {
            const int wx = w0 + j - 1;
            if ((unsigned)wx < (unsigned)Ww)
                rv[j] = *(const float2*)&g_xh[((size_t)(b * HW + hy * Ww + wx)) * Cc + c];
            else
                rv[j] = make_float2(0.f, 0.f);
        }
        #pragma unroll
        for (int px = 0; px < 8; px++) {
            a0[px] = fmaf(rv[px].x,     wv0.x, a0[px]);
            a1[px] = fmaf(rv[px].y,     wv0.y, a1[px]);
            a0[px] = fmaf(rv[px + 1].x, wv1.x, a0[px]);
            a1[px] = fmaf(rv[px + 1].y, wv1.y, a1[px]);
            a0[px] = fmaf(rv[px + 2].x, wv2.x, a0[px]);
            a1[px] = fmaf(rv[px + 2].y, wv2.y, a1[px]);
        }
    }
    const float2 bb2 = *(const float2*)&bdw[c];
    #pragma unroll
    for (int px = 0; px < 8; px++) { a0[px] += bb2.x; a1[px] += bb2.y; }

    #pragma unroll
    for (int px = 0; px < 8; px++) {
        float part = a0[px] + a1[px];
        #pragma unroll
        for (int s = 16; s > 0; s >>= 1) part += __shfl_xor_sync(0xffffffffu, part, s);
        if (lane == 0) sA[wid][px] = part;
    }
    __syncthreads();
    float mu[8];
    #pragma unroll
    for (int px = 0; px < 8; px++) {
        float s = 0.f;
        #pragma unroll
        for (int i = 0; i < 8; i++) s += sA[i][px];
        mu[px] = s * (1.0f / 512.0f);
    }
    #pragma unroll
    for (int px = 0; px < 8; px++) {
        const float d0 = a0[px] - mu[px];
        const float d1 = a1[px] - mu[px];
        float vp = d0 * d0 + d1 * d1;
        #pragma unroll
        for (int s = 16; s > 0; s >>= 1) vp += __shfl_xor_sync(0xffffffffu, vp, s);
        if (lane == 0) sB[wid][px] = vp;
    }
    __syncthreads();

    const float2 gg = *(const float2*)&lng[c];
    const float2 be = *(const float2*)&lnb[c];
    #pragma unroll
    for (int px = 0; px < 8; px++) {
        float var = 0.f;
        #pragma unroll
        for (int i = 0; i < 8; i++) var += sB[i][px];
        var *= (1.0f / 512.0f);
        const float rstd = rsqrtf(var + 1e-6f);
        float o0 = (a0[px] - mu[px]) * rstd * gg.x + be.x;
        float o1 = (a1[px] - mu[px]) * rstd * gg.y + be.y;
        o0 = 0.5f * o0 * (1.0f + erff(o0 * 0.7071067811865475f));
        o1 = 0.5f * o1 * (1.0f + erff(o1 * 0.7071067811865475f));
        *(float2*)&g_x1[(size_t)(m0 + px) * Cc + c] = make_float2(tf32r(o0), tf32r(o1));
    }
}

// ---------------- DCNv3 sampling + fused softmax (fp16 xp) -----------------
__device__ __forceinline__ float dcn_fetch(const __half* __restrict__ base,
                                           int yu, int xu) {
    if ((unsigned)yu < (unsigned)Hh && (unsigned)xu < (unsigned)Ww)
        return __half2float(base[(size_t)(yu * Ww + xu) * Cc]);
    return 0.f;
}

__global__ __launch_bounds__(256)
void dcn_sample() {
    const int gid = blockIdx.x * 8 + (threadIdx.x >> 5);
    const int lane = threadIdx.x & 31;
    if (gid >= Mtot * Gg) return;
    const int m = gid >> 4;
    const int g = gid & 15;
    const int b = m / HW;
    const int hw = m - b * HW;
    const int h = hw / Ww;
    const int w = hw - h * Ww;

    const float* offp = g_om + (size_t)m * Ncat + g * (Pp * 2);
    const float* mskp = g_om + (size_t)m * Ncat + Noff + g * Pp;
    const __half* base = g_xph + (size_t)b * HW * Cc + g * GC + lane;

    float logit[Pp];
    float mx = -1e30f;
    #pragma unroll
    for (int p = 0; p < Pp; p++) { logit[p] = mskp[p]; mx = fmaxf(mx, logit[p]); }
    float ssum = 0.f;
    #pragma unroll
    for (int p = 0; p < Pp; p++) { logit[p] = expf(logit[p] - mx); ssum += logit[p]; }
    const float sinv = 1.0f / ssum;

    float acc = 0.f;
    #pragma unroll
    for (int p = 0; p < Pp; p++) {
        const int kx = p / 3;
        const int ky = p - kx * 3;
        const float2 o2 = *(const float2*)&offp[2 * p];
        const float fx = (float)(w + kx - 1) + o2.x;
        const float fy = (float)(h + ky - 1) + o2.y;
        const float x0f = floorf(fx);
        const float y0f = floorf(fy);
        const float txf = fx - x0f;
        const float tyf = fy - y0f;
        const int x0 = (int)x0f;
        const int y0 = (int)y0f;
        const float msk = logit[p] * sinv;
        const float v00 = dcn_fetch(base, y0,     x0);
        const float v01 = dcn_fetch(base, y0,     x0 + 1);
        const float v10 = dcn_fetch(base, y0 + 1, x0);
        const float v11 = dcn_fetch(base, y0 + 1, x0 + 1);
        const float s = (1.f - tyf) * (1.f - txf) * v00
                      + (1.f - tyf) * txf * v01
                      + tyf * (1.f - txf) * v10
                      + tyf * txf * v11;
        acc = fmaf(msk, s, acc);
    }
    g_ys[(size_t)m * Cc + g * GC + lane] = tf32r(acc);
}

// ---------------- host launch ----------------------------------------------
extern "C" void kernel_launch(void* const* d_in, const int* in_sizes, int n_in,
                              void* d_out, int out_size) {
    const float* x      = (const float*)d_in[0];
    const float* w_in   = (const float*)d_in[1];
    const float* b_in   = (const float*)d_in[2];
    const float* w_dw   = (const float*)d_in[3];
    const float* b_dw   = (const float*)d_in[4];
    const float* ln_g   = (const float*)d_in[5];
    const float* ln_b   = (const float*)d_in[6];
    const float* w_off  = (const float*)d_in[7];
    const float* b_off  = (const float*)d_in[8];
    const float* w_mask = (const float*)d_in[9];
    const float* b_mask = (const float*)d_in[10];
    const float* w_out  = (const float*)d_in[11];
    const float* b_out  = (const float*)d_in[12];
    const float* bn_g   = (const float*)d_in[13];
    const float* bn_b   = (const float*)d_in[14];
    const float* bn_m   = (const float*)d_in[15];
    const float* bn_v   = (const float*)d_in[16];

    // one-time setup (first call is the uncaptured correctness run)
    static int inited = 0;
    static cudaStream_t s1;
    static cudaEvent_t evS, evT, evP, ev2;
    if (!inited) {
        cudaFuncSetAttribute(gemm_in, cudaFuncAttributeMaxDynamicSharedMemorySize, TF_DSMEM);
        cudaFuncSetAttribute(gemm_om, cudaFuncAttributeMaxDynamicSharedMemorySize, TF_DSMEM);
        cudaFuncSetAttribute(gemm_out, cudaFuncAttributeMaxDynamicSharedMemorySize, TF_DSMEM);
        cudaStreamCreateWithFlags(&s1, cudaStreamNonBlocking);
        cudaEventCreateWithFlags(&evS, cudaEventDisableTiming);
        cudaEventCreateWithFlags(&evT, cudaEventDisableTiming);
        cudaEventCreateWithFlags(&evP, cudaEventDisableTiming);
        cudaEventCreateWithFlags(&ev2, cudaEventDisableTiming);
        inited = 1;
    }

    // fork s1 from the main (capture) stream
    cudaEventRecord(evS, 0);
    cudaStreamWaitEvent(s1, evS, 0);

    // s1: fused weight prep
    prep_weights<<<3072, 256, 0, s1>>>(w_in, w_out, w_off, b_off, w_mask, b_mask);
    cudaEventRecord(evP, s1);

    // s0: NCHW -> NHWC (+ tf32 copy)
    nchw_to_nhwc<<<dim3(HW / 32, Cc / 32, Bn), dim3(32, 8)>>>(x);
    cudaEventRecord(evT, 0);

    // s1: depthwise branch + offset/mask GEMM (after transpose)
    cudaStreamWaitEvent(s1, evT, 0);
    dw_ln_gelu<<<Mtot / 8, 256, 0, s1>>>(w_dw, b_dw, ln_g, ln_b);
    gemm_om<<<dim3(NPAD / 128, Mtot / 128), 256, TF_DSMEM, s1>>>();
    cudaEventRecord(ev2, s1);

    // s0: input_proj — overlaps with dw+gemm_om on s1
    cudaStreamWaitEvent(0, evP, 0);
    gemm_in<<<dim3(Cc / 128, Mtot / 128), 256, TF_DSMEM>>>(b_in);

    // join: dcn needs xp (s0) + om (s1)
    cudaStreamWaitEvent(0, ev2, 0);
    dcn_sample<<<(Mtot * Gg) / 8, 256>>>();
    // output_proj + BN + SiLU (tf32)
    gemm_out<<<dim3(Cc / 128, Mtot / 128), 256, TF_DSMEM>>>(b_out, bn_g, bn_b,
                                                            bn_m, bn_v, (float*)d_out);
}

// round 14
// speedup vs baseline: 1.2046x; 1.2046x over previous
#include <cuda_runtime.h>
#include <cuda_bf16.h>
#include <cuda_fp16.h>
#include <math.h>
#include <cstdint>

typedef unsigned int u32;
typedef unsigned short u16;
typedef unsigned long long u64;

// Problem constants
#define Bn 4
#define Cc 512
#define Hh 56
#define Ww 56
#define Gg 16
#define Pp 9
#define GC 32
#define HW 3136          // 56*56
#define Mtot 12544       // B*H*W
#define Noff 288         // G*P*2
#define Nmsk 144         // G*P
#define Ncat 432         // Noff+Nmsk
#define NPAD 512         // Ncat padded to 128 multiple

// ---------------- scratch (device globals; no allocation allowed) ----------
__device__ float  g_xh[Mtot * Cc];        // NHWC input fp32 (for depthwise)
__device__ float  g_xa[Mtot * Cc];        // tf32-rounded NHWC (GEMM1 A)
__device__ __half g_xph[Mtot * Cc];       // input_proj output fp16 (dcn only)
__device__ float  g_x1[Mtot * Cc];        // dw+LN+GELU, tf32-rounded (GEMM2 A)
__device__ float  g_om[Mtot * Ncat];      // [offset|mask logits]
__device__ float  g_ys[Mtot * Cc];        // DCN output, tf32-rounded (GEMM3 A)
__device__ float  g_winT[Cc * Cc];        // w_in^T tf32-rounded: [n][k]
__device__ float  g_wcatT[NPAD * Cc];     // concat weight^T tf32-rounded: [n][k]
__device__ float  g_woutT[Cc * Cc];       // w_out^T tf32-rounded: [n][k]
__device__ float  g_bcat[NPAD];

// ---------------- helpers ---------------------------------------------------
__device__ __forceinline__ float tf32r(float v) {
    u32 r;
    asm("cvt.rna.tf32.f32 %0, %1;" : "=r"(r) : "f"(v));
    return __uint_as_float(r);
}
__device__ __forceinline__ void ldmA4(u32* r, u32 addr) {
    asm volatile("ldmatrix.sync.aligned.m8n8.x4.shared.b16 {%0,%1,%2,%3}, [%4];\n"
                 : "=r"(r[0]), "=r"(r[1]), "=r"(r[2]), "=r"(r[3]) : "r"(addr));
}
__device__ __forceinline__ void ldmB4(u32* r, u32 addr) {
    asm volatile("ldmatrix.sync.aligned.m8n8.x4.shared.b16 {%0,%1,%2,%3}, [%4];\n"
                 : "=r"(r[0]), "=r"(r[1]), "=r"(r[2]), "=r"(r[3]) : "r"(addr));
}
__device__ __forceinline__ void mma_tf32(float* c, const u32* a, const u32* b) {
    asm volatile("mma.sync.aligned.m16n8k8.row.col.f32.tf32.tf32.f32 "
                 "{%0,%1,%2,%3}, {%4,%5,%6,%7}, {%8,%9}, {%0,%1,%2,%3};\n"
                 : "+f"(c[0]), "+f"(c[1]), "+f"(c[2]), "+f"(c[3])
                 : "r"(a[0]), "r"(a[1]), "r"(a[2]), "r"(a[3]), "r"(b[0]), "r"(b[1]));
}
__device__ __forceinline__ void cpa16(u32 dst, const void* src) {
    asm volatile("cp.async.cg.shared.global [%0], [%1], 16;\n" :: "r"(dst), "l"(src));
}
__device__ __forceinline__ void cpcommit() { asm volatile("cp.async.commit_group;\n"); }
__device__ __forceinline__ void cpwait0() { asm volatile("cp.async.wait_group 0;\n"); }
__device__ __forceinline__ void cpwait1() { asm volatile("cp.async.wait_group 1;\n"); }

// ---------------- fused weight prep -----------------------------------------
__global__ __launch_bounds__(256)
void prep_weights(const float* __restrict__ w_in, const float* __restrict__ w_out,
                  const float* __restrict__ w_off, const float* __restrict__ b_off,
                  const float* __restrict__ w_mask, const float* __restrict__ b_mask) {
    const int seg = blockIdx.x >> 10;
    const int i = ((blockIdx.x & 1023) << 8) + threadIdx.x;
    if (seg == 0) {
        const int k = i >> 9;
        const int n = i & 511;
        g_winT[n * Cc + k] = tf32r(w_in[i]);
    } else if (seg == 1) {
        const int k = i >> 9;
        const int n = i & 511;
        g_woutT[n * Cc + k] = tf32r(w_out[i]);
    } else {
        const int n = i >> 9;
        const int k = i & 511;
        float v = 0.f;
        if (n < Noff) v = w_off[k * Noff + n];
        else if (n < Ncat) v = w_mask[k * Nmsk + (n - Noff)];
        g_wcatT[i] = tf32r(v);
        if (i < NPAD)
            g_bcat[i] = (i < Noff) ? b_off[i] : (i < Ncat ? b_mask[i - Noff] : 0.f);
    }
}

// ---------------- NCHW -> NHWC transpose (+ tf32 copy) ----------------------
__global__ __launch_bounds__(256)
void nchw_to_nhwc(const float* __restrict__ x) {
    __shared__ float tile[32][33];
    const int bb = blockIdx.z;
    const int hw0 = blockIdx.x * 32;
    const int c0 = blockIdx.y * 32;
    const int tx = threadIdx.x;
    const int ty = threadIdx.y;
    const float* xb = x + (size_t)bb * Cc * HW;
    #pragma unroll
    for (int i = 0; i < 32; i += 8)
        tile[ty + i][tx] = xb[(size_t)(c0 + ty + i) * HW + hw0 + tx];
    __syncthreads();
    #pragma unroll
    for (int i = 0; i < 32; i += 8) {
        const size_t idx = ((size_t)bb * HW + hw0 + ty + i) * Cc + c0 + tx;
        const float v = tile[tx][ty + i];
        g_xh[idx] = v;
        g_xa[idx] = tf32r(v);
    }
}

// ================= tf32 GEMM: BM=128 BN=128 BK=32, 3-stage ==================
#define TF_STG 32768
#define TF_DSMEM (3 * TF_STG)

__device__ __forceinline__ void tf_fill(const float* __restrict__ A,
                                        const float* __restrict__ B,
                                        int bm, int bn, int kt, u32 stg) {
    const int t = threadIdx.x;
    const int row = t >> 1;
    const int cb = (t & 1) * 4;
    const size_t ka = (size_t)(bm + row) * Cc + kt * 32;
    const size_t kb = (size_t)(bn + row) * Cc + kt * 32;
    #pragma unroll
    for (int i = 0; i < 4; i++) {
        const int c = cb + i;
        const u32 d = (u32)(row * 128 + ((c ^ (row & 7)) << 4));
        cpa16(stg + d,         (const void*)(A + ka + c * 4));
        cpa16(stg + 16384 + d, (const void*)(B + kb + c * 4));
    }
    cpcommit();
}

__device__ __forceinline__ void tf_compute(u32 stg, int wm, int wn, int lane,
                                           float acc[4][4][4]) {
    const u32 stgB = stg + 16384;
    const int arow7 = lane & 7;
    const int arow8 = ((lane >> 3) & 1) * 8;
    const int achk = lane >> 4;
    const int brow8 = (lane >> 4) * 8;
    const int bchk = (lane >> 3) & 1;
    #pragma unroll
    for (int ks = 0; ks < 4; ks++) {
        u32 a[4][4];
        #pragma unroll
        for (int mf = 0; mf < 4; mf++) {
            const int row = wm + mf * 16 + arow7 + arow8;
            const int ch = 2 * ks + achk;
            ldmA4(a[mf], stg + (u32)(row * 128 + ((ch ^ (row & 7)) << 4)));
        }
        u32 b4[2][4];
        #pragma unroll
        for (int j = 0; j < 2; j++) {
            const int row = wn + (2 * j) * 8 + brow8 + arow7;
            const int ch = 2 * ks + bchk;
            ldmB4(b4[j], stgB + (u32)(row * 128 + ((ch ^ (row & 7)) << 4)));
        }
        #pragma unroll
        for (int mf = 0; mf < 4; mf++) {
            #pragma unroll
            for (int j = 0; j < 2; j++) {
                mma_tf32(acc[mf][2 * j + 0], a[mf], &b4[j][0]);
                mma_tf32(acc[mf][2 * j + 1], a[mf], &b4[j][2]);
            }
        }
    }
}

__device__ __forceinline__ void tf_core(const float* __restrict__ A,
                                        const float* __restrict__ B,
                                        int bm, int bn, u32 smbase,
                                        float acc[4][4][4]) {
    const int wid = threadIdx.x >> 5;
    const int lane = threadIdx.x & 31;
    const int wm = (wid & 1) * 64;
    const int wn = (wid >> 1) * 32;
    const u32 st[3] = {smbase, smbase + TF_STG, smbase + 2 * TF_STG};
    tf_fill(A, B, bm, bn, 0, st[0]);
    tf_fill(A, B, bm, bn, 1, st[1]);
    #pragma unroll 1
    for (int kt = 0; kt < 16; kt++) {
        if (kt == 15) cpwait0(); else cpwait1();
        __syncthreads();
        if (kt + 2 < 16) {
            int s2 = kt + 2; s2 -= (s2 / 3) * 3;
            tf_fill(A, B, bm, bn, kt + 2, st[s2]);
        }
        int s = kt; s -= (s / 3) * 3;
        tf_compute(st[s], wm, wn, lane, acc);
    }
}

// ---- GEMM 1 (tf32): xp(fp16) = xa @ winT^T + b_in --------------------------
__global__ __launch_bounds__(256, 2)
void gemm_in(const float* __restrict__ bias) {
    extern __shared__ char smem[];
    const u32 smbase = (u32)__cvta_generic_to_shared(smem);
    float acc[4][4][4];
    #pragma unroll
    for (int i = 0; i < 4; i++)
        #pragma unroll
        for (int j = 0; j < 4; j++)
            #pragma unroll
            for (int q = 0; q < 4; q++) acc[i][j][q] = 0.f;
    const int bm = blockIdx.y * 128;
    const int bn = blockIdx.x * 128;
    tf_core(g_xa, g_winT, bm, bn, smbase, acc);

    const int wid = threadIdx.x >> 5;
    const int lane = threadIdx.x & 31;
    const int wm = (wid & 1) * 64;
    const int wn = (wid >> 1) * 32;
    const int r0 = lane >> 2;
    const int c0 = (lane & 3) * 2;
    #pragma unroll
    for (int mf = 0; mf < 4; mf++) {
        #pragma unroll
        for (int nf = 0; nf < 4; nf++) {
            const int col = bn + wn + nf * 8 + c0;
            #pragma unroll
            for (int half = 0; half < 2; half++) {
                const int row = bm + wm + mf * 16 + r0 + half * 8;
                const float y0 = acc[mf][nf][half * 2 + 0] + bias[col];
                const float y1 = acc[mf][nf][half * 2 + 1] + bias[col + 1];
                *(__half2*)&g_xph[(size_t)row * Cc + col] = __floats2half2_rn(y0, y1);
            }
        }
    }
}

// ---- GEMM 2 (tf32): g_om = x1 @ wcatT^T + bcat  (N=512 pad, store 432) -----
__global__ __launch_bounds__(256, 2)
void gemm_om() {
    extern __shared__ char smem[];
    const u32 smbase = (u32)__cvta_generic_to_shared(smem);
    float acc[4][4][4];
    #pragma unroll
    for (int i = 0; i < 4; i++)
        #pragma unroll
        for (int j = 0; j < 4; j++)
            #pragma unroll
            for (int q = 0; q < 4; q++) acc[i][j][q] = 0.f;
    const int bm = blockIdx.y * 128;
    const int bn = blockIdx.x * 128;
    tf_core(g_x1, g_wcatT, bm, bn, smbase, acc);

    const int wid = threadIdx.x >> 5;
    const int lane = threadIdx.x & 31;
    const int wm = (wid & 1) * 64;
    const int wn = (wid >> 1) * 32;
    const int r0 = lane >> 2;
    const int c0 = (lane & 3) * 2;
    #pragma unroll
    for (int mf = 0; mf < 4; mf++) {
        #pragma unroll
        for (int nf = 0; nf < 4; nf++) {
            const int col = bn + wn + nf * 8 + c0;
            if (col < Ncat) {
                #pragma unroll
                for (int half = 0; half < 2; half++) {
                    const int row = bm + wm + mf * 16 + r0 + half * 8;
                    float2 v;
                    v.x = acc[mf][nf][half * 2 + 0] + g_bcat[col];
                    v.y = acc[mf][nf][half * 2 + 1] + g_bcat[col + 1];
                    *(float2*)&g_om[(size_t)row * Ncat + col] = v;
                }
            }
        }
    }
}

// ---- GEMM 3 (tf32): out = SiLU(BN(ys @ woutT^T + b_out)) in NCHW -----------
__global__ __launch_bounds__(256, 2)
void gemm_out(const float* __restrict__ bias,
              const float* __restrict__ bn_g, const float* __restrict__ bn_b,
              const float* __restrict__ bn_m, const float* __restrict__ bn_v,
              float* __restrict__ out) {
    extern __shared__ char smem[];
    const u32 smbase = (u32)__cvta_generic_to_shared(smem);
    float acc[4][4][4];
    #pragma unroll
    for (int i = 0; i < 4; i++)
        #pragma unroll
        for (int j = 0; j < 4; j++)
            #pragma unroll
            for (int q = 0; q < 4; q++) acc[i][j][q] = 0.f;
    const int bm = blockIdx.y * 128;
    const int bn = blockIdx.x * 128;
    tf_core(g_ys, g_woutT, bm, bn, smbase, acc);

    const int wid = threadIdx.x >> 5;
    const int lane = threadIdx.x & 31;
    const int wm = (wid & 1) * 64;
    const int wn = (wid >> 1) * 32;
    const int r0 = lane >> 2;
    const int c0 = (lane & 3) * 2;
    #pragma unroll
    for (int mf = 0; mf < 4; mf++) {
        #pragma unroll
        for (int nf = 0; nf < 4; nf++) {
            const int col = bn + wn + nf * 8 + c0;
            const float s0 = bn_g[col] * rsqrtf(bn_v[col] + 1e-5f);
            const float s1 = bn_g[col + 1] * rsqrtf(bn_v[col + 1] + 1e-5f);
            #pragma unroll
            for (int half = 0; half < 2; half++) {
                const int row = bm + wm + mf * 16 + r0 + half * 8;
                const int bidx = row / HW;
                const int hw = row - bidx * HW;
                float y0 = acc[mf][nf][half * 2 + 0] + bias[col];
                float y1 = acc[mf][nf][half * 2 + 1] + bias[col + 1];
                y0 = (y0 - bn_m[col]) * s0 + bn_b[col];
                y1 = (y1 - bn_m[col + 1]) * s1 + bn_b[col + 1];
                out[((size_t)bidx * Cc + col) * HW + hw]     = y0 / (1.0f + expf(-y0));
                out[((size_t)bidx * Cc + col + 1) * HW + hw] = y1 / (1.0f + expf(-y1));
            }
        }
    }
}

// ------- depthwise 3x3 + LN + GELU: 8-pixel sliding window per block -------
__global__ __launch_bounds__(256)
void dw_ln_gelu(const float* __restrict__ wdw, const float* __restrict__ bdw,
                const float* __restrict__ lng, const float* __restrict__ lnb) {
    __shared__ float sA[8][8];
    __shared__ float sB[8][8];
    const int m0 = blockIdx.x * 8;
    const int b = m0 / HW;
    const int hw0 = m0 - b * HW;
    const int h = hw0 / Ww;
    const int w0 = hw0 - h * Ww;
    const int tid = threadIdx.x;
    const int wid = tid >> 5;
    const int lane = tid & 31;
    const int c = tid * 2;

    float a0[8], a1[8];
    #pragma unroll
    for (int i = 0; i < 8; i++) { a0[i] = 0.f; a1[i] = 0.f; }

    #pragma unroll
    for (int ky = 0; ky < 3; ky++) {
        const int hy = h + ky - 1;
        if ((unsigned)hy >= (unsigned)Hh) continue;
        const float2 wv0 = *(const float2*)&wdw[(ky * 3 + 0) * Cc + c];
        const float2 wv1 = *(const float2*)&wdw[(ky * 3 + 1) * Cc + c];
        const float2 wv2 = *(const float2*)&wdw[(ky * 3 + 2) * Cc + c];
        float2 rv[10];
        #pragma unroll
        for (int j = 0; j < 10; j++) {
            const int wx = w0 + j - 1;
            if ((unsigned)wx < (unsigned)Ww)
                rv[j] = *(const float2*)&g_xh[((size_t)(b * HW + hy * Ww + wx)) * Cc + c];
            else
                rv[j] = make_float2(0.f, 0.f);
        }
        #pragma unroll
        for (int px = 0; px < 8; px++) {
            a0[px] = fmaf(rv[px].x,     wv0.x, a0[px]);
            a1[px] = fmaf(rv[px].y,     wv0.y, a1[px]);
            a0[px] = fmaf(rv[px + 1].x, wv1.x, a0[px]);
            a1[px] = fmaf(rv[px + 1].y, wv1.y, a1[px]);
            a0[px] = fmaf(rv[px + 2].x, wv2.x, a0[px]);
            a1[px] = fmaf(rv[px + 2].y, wv2.y, a1[px]);
        }
    }
    const float2 bb2 = *(const float2*)&bdw[c];
    #pragma unroll
    for (int px = 0; px < 8; px++) { a0[px] += bb2.x; a1[px] += bb2.y; }

    #pragma unroll
    for (int px = 0; px < 8; px++) {
        float part = a0[px] + a1[px];
        #pragma unroll
        for (int s = 16; s > 0; s >>= 1) part += __shfl_xor_sync(0xffffffffu, part, s);
        if (lane == 0) sA[wid][px] = part;
    }
    __syncthreads();
    float mu[8];
    #pragma unroll
    for (int px = 0; px < 8; px++) {
        float s = 0.f;
        #pragma unroll
        for (int i = 0; i < 8; i++) s += sA[i][px];
        mu[px] = s * (1.0f / 512.0f);
    }
    #pragma unroll
    for (int px = 0; px < 8; px++) {
        const float d0 = a0[px] - mu[px];
        const float d1 = a1[px] - mu[px];
        float vp = d0 * d0 + d1 * d1;
        #pragma unroll
        for (int s = 16; s > 0; s >>= 1) vp += __shfl_xor_sync(0xffffffffu, vp, s);
        if (lane == 0) sB[wid][px] = vp;
    }
    __syncthreads();

    const float2 gg = *(const float2*)&lng[c];
    const float2 be = *(const float2*)&lnb[c];
    #pragma unroll
    for (int px = 0; px < 8; px++) {
        float var = 0.f;
        #pragma unroll
        for (int i = 0; i < 8; i++) var += sB[i][px];
        var *= (1.0f / 512.0f);
        const float rstd = rsqrtf(var + 1e-6f);
        float o0 = (a0[px] - mu[px]) * rstd * gg.x + be.x;
        float o1 = (a1[px] - mu[px]) * rstd * gg.y + be.y;
        o0 = 0.5f * o0 * (1.0f + erff(o0 * 0.7071067811865475f));
        o1 = 0.5f * o1 * (1.0f + erff(o1 * 0.7071067811865475f));
        *(float2*)&g_x1[(size_t)(m0 + px) * Cc + c] = make_float2(tf32r(o0), tf32r(o1));
    }
}

// ------- DCNv3 sampling + fused softmax: warp = (pixel, group-pair) --------
// Lanes 0-15 serve group 2*gp (2 fp16 channels/lane), lanes 16-31 group 2*gp+1.
// Halves total scalar work vs one-warp-per-(pixel,group).
__global__ __launch_bounds__(256)
void dcn_sample() {
    const int wuid = blockIdx.x * 8 + (threadIdx.x >> 5);
    const int lane = threadIdx.x & 31;
    if (wuid >= Mtot * (Gg / 2)) return;
    const int m = wuid >> 3;              // Gg/2 = 8 pairs
    const int gp = wuid & 7;
    const int g = gp * 2 + (lane >> 4);
    const int ch = (lane & 15) * 2;
    const int b = m / HW;
    const int hw = m - b * HW;
    const int h = hw / Ww;
    const int w = hw - h * Ww;

    const float* offp = g_om + (size_t)m * Ncat + g * (Pp * 2);
    const float* mskp = g_om + (size_t)m * Ncat + Noff + g * Pp;
    const __half* base = g_xph + (size_t)b * HW * Cc + g * GC + ch;

    float logit[Pp];
    float mx = -1e30f;
    #pragma unroll
    for (int p = 0; p < Pp; p++) { logit[p] = mskp[p]; mx = fmaxf(mx, logit[p]); }
    float ssum = 0.f;
    #pragma unroll
    for (int p = 0; p < Pp; p++) { logit[p] = expf(logit[p] - mx); ssum += logit[p]; }
    const float sinv = 1.0f / ssum;

    float acc0 = 0.f, acc1 = 0.f;
    #pragma unroll
    for (int p = 0; p < Pp; p++) {
        const int kx = p / 3;
        const int ky = p - kx * 3;
        const float2 o2 = *(const float2*)&offp[2 * p];
        const float fx = (float)(w + kx - 1) + o2.x;
        const float fy = (float)(h + ky - 1) + o2.y;
        const float x0f = floorf(fx);
        const float y0f = floorf(fy);
        const float txf = fx - x0f;
        const float tyf = fy - y0f;
        const int x0 = (int)x0f;
        const int y0 = (int)y0f;
        const float msk = logit[p] * sinv;
        float2 v00 = make_float2(0.f, 0.f), v01 = v00, v10 = v00, v11 = v00;
        const bool yi0 = (unsigned)y0 < (unsigned)Hh;
        const bool yi1 = (unsigned)(y0 + 1) < (unsigned)Hh;
        const bool xi0 = (unsigned)x0 < (unsigned)Ww;
        const bool xi1 = (unsigned)(x0 + 1) < (unsigned)Ww;
        if (yi0 && xi0) v00 = __half22float2(*(const __half2*)&base[(size_t)(y0 * Ww + x0) * Cc]);
        if (yi0 && xi1) v01 = __half22float2(*(const __half2*)&base[(size_t)(y0 * Ww + x0 + 1) * Cc]);
        if (yi1 && xi0) v10 = __half22float2(*(const __half2*)&base[(size_t)((y0 + 1) * Ww + x0) * Cc]);
        if (yi1 && xi1) v11 = __half22float2(*(const __half2*)&base[(size_t)((y0 + 1) * Ww + x0 + 1) * Cc]);
        const float w00 = (1.f - tyf) * (1.f - txf);
        const float w01 = (1.f - tyf) * txf;
        const float w10 = tyf * (1.f - txf);
        const float w11 = tyf * txf;
        const float s0 = w00 * v00.x + w01 * v01.x + w10 * v10.x + w11 * v11.x;
        const float s1 = w00 * v00.y + w01 * v01.y + w10 * v10.y + w11 * v11.y;
        acc0 = fmaf(msk, s0, acc0);
        acc1 = fmaf(msk, s1, acc1);
    }
    *(float2*)&g_ys[(size_t)m * Cc + g * GC + ch] =
        make_float2(tf32r(acc0), tf32r(acc1));
}

// ---------------- host launch ----------------------------------------------
extern "C" void kernel_launch(void* const* d_in, const int* in_sizes, int n_in,
                              void* d_out, int out_size) {
    const float* x      = (const float*)d_in[0];
    const float* w_in   = (const float*)d_in[1];
    const float* b_in   = (const float*)d_in[2];
    const float* w_dw   = (const float*)d_in[3];
    const float* b_dw   = (const float*)d_in[4];
    const float* ln_g   = (const float*)d_in[5];
    const float* ln_b   = (const float*)d_in[6];
    const float* w_off  = (const float*)d_in[7];
    const float* b_off  = (const float*)d_in[8];
    const float* w_mask = (const float*)d_in[9];
    const float* b_mask = (const float*)d_in[10];
    const float* w_out  = (const float*)d_in[11];
    const float* b_out  = (const float*)d_in[12];
    const float* bn_g   = (const float*)d_in[13];
    const float* bn_b   = (const float*)d_in[14];
    const float* bn_m   = (const float*)d_in[15];
    const float* bn_v   = (const float*)d_in[16];

    // one-time setup (first call is the uncaptured correctness run)
    static int inited = 0;
    static cudaStream_t s1;
    static cudaEvent_t evS, evT, evP, ev2;
    if (!inited) {
        cudaFuncSetAttribute(gemm_in, cudaFuncAttributeMaxDynamicSharedMemorySize, TF_DSMEM);
        cudaFuncSetAttribute(gemm_om, cudaFuncAttributeMaxDynamicSharedMemorySize, TF_DSMEM);
        cudaFuncSetAttribute(gemm_out, cudaFuncAttributeMaxDynamicSharedMemorySize, TF_DSMEM);
        cudaStreamCreateWithFlags(&s1, cudaStreamNonBlocking);
        cudaEventCreateWithFlags(&evS, cudaEventDisableTiming);
        cudaEventCreateWithFlags(&evT, cudaEventDisableTiming);
        cudaEventCreateWithFlags(&evP, cudaEventDisableTiming);
        cudaEventCreateWithFlags(&ev2, cudaEventDisableTiming);
        inited = 1;
    }

    // fork s1 from the main (capture) stream
    cudaEventRecord(evS, 0);
    cudaStreamWaitEvent(s1, evS, 0);

    // s1: fused weight prep
    prep_weights<<<3072, 256, 0, s1>>>(w_in, w_out, w_off, b_off, w_mask, b_mask);
    cudaEventRecord(evP, s1);

    // s0: NCHW -> NHWC (+ tf32 copy)
    nchw_to_nhwc<<<dim3(HW / 32, Cc / 32, Bn), dim3(32, 8)>>>(x);
    cudaEventRecord(evT, 0);

    // s1: depthwise branch + offset/mask GEMM (after transpose)
    cudaStreamWaitEvent(s1, evT, 0);
    dw_ln_gelu<<<Mtot / 8, 256, 0, s1>>>(w_dw, b_dw, ln_g, ln_b);
    gemm_om<<<dim3(NPAD / 128, Mtot / 128), 256, TF_DSMEM, s1>>>();
    cudaEventRecord(ev2, s1);

    // s0: input_proj — overlaps with dw+gemm_om on s1
    cudaStreamWaitEvent(0, evP, 0);
    gemm_in<<<dim3(Cc / 128, Mtot / 128), 256, TF_DSMEM>>>(b_in);

    // join: dcn needs xp (s0) + om (s1)
    cudaStreamWaitEvent(0, ev2, 0);
    dcn_sample<<<(Mtot * (Gg / 2)) / 8, 256>>>();
    // output_proj + BN + SiLU (tf32)
    gemm_out<<<dim3(Cc / 128, Mtot / 128), 256, TF_DSMEM>>>(b_out, bn_g, bn_b,
                                                            bn_m, bn_v, (float*)d_out);
}

// round 15
// speedup vs baseline: 1.5938x; 1.3231x over previous
#include <cuda_runtime.h>
#include <cuda_bf16.h>
#include <cuda_fp16.h>
#include <math.h>
#include <cstdint>

typedef unsigned int u32;
typedef unsigned short u16;
typedef unsigned long long u64;

// Problem constants
#define Bn 4
#define Cc 512
#define Hh 56
#define Ww 56
#define Gg 16
#define Pp 9
#define GC 32
#define HW 3136          // 56*56
#define Mtot 12544       // B*H*W
#define Noff 288         // G*P*2
#define Nmsk 144         // G*P
#define Ncat 432         // Noff+Nmsk
#define NPAD 512         // Ncat padded to 128 multiple

// ---------------- scratch (device globals; no allocation allowed) ----------
__device__ float  g_xh[Mtot * Cc];        // NHWC input fp32 (for depthwise)
__device__ __half g_xa[Mtot * Cc];        // fp16 NHWC (GEMM1 A)
__device__ __half g_xph[Mtot * Cc];       // input_proj output fp16 (dcn only)
__device__ __half g_x1h[Mtot * Cc];       // dw+LN+GELU fp16 (GEMM2 A)
__device__ float  g_om[Mtot * Ncat];      // [offset|mask logits]
__device__ __half g_ysh[Mtot * Cc];       // DCN output fp16 (GEMM3 A)
__device__ __half g_winT[Cc * Cc];        // w_in^T fp16: [n][k]
__device__ __half g_wcatT[NPAD * Cc];     // concat weight^T fp16: [n][k]
__device__ __half g_woutT[Cc * Cc];       // w_out^T fp16: [n][k]
__device__ float  g_bcat[NPAD];

// ---------------- helpers ---------------------------------------------------
__device__ __forceinline__ void ldmA4(u32* r, u32 addr) {
    asm volatile("ldmatrix.sync.aligned.m8n8.x4.shared.b16 {%0,%1,%2,%3}, [%4];\n"
                 : "=r"(r[0]), "=r"(r[1]), "=r"(r[2]), "=r"(r[3]) : "r"(addr));
}
__device__ __forceinline__ void ldmB4(u32* r, u32 addr) {
    asm volatile("ldmatrix.sync.aligned.m8n8.x4.shared.b16 {%0,%1,%2,%3}, [%4];\n"
                 : "=r"(r[0]), "=r"(r[1]), "=r"(r[2]), "=r"(r[3]) : "r"(addr));
}
__device__ __forceinline__ void mma_f16(float* c, const u32* a, const u32* b) {
    asm volatile("mma.sync.aligned.m16n8k16.row.col.f32.f16.f16.f32 "
                 "{%0,%1,%2,%3}, {%4,%5,%6,%7}, {%8,%9}, {%0,%1,%2,%3};\n"
                 : "+f"(c[0]), "+f"(c[1]), "+f"(c[2]), "+f"(c[3])
                 : "r"(a[0]), "r"(a[1]), "r"(a[2]), "r"(a[3]), "r"(b[0]), "r"(b[1]));
}
__device__ __forceinline__ void cpa16(u32 dst, const void* src) {
    asm volatile("cp.async.cg.shared.global [%0], [%1], 16;\n" :: "r"(dst), "l"(src));
}
__device__ __forceinline__ void cpcommit() { asm volatile("cp.async.commit_group;\n"); }
__device__ __forceinline__ void cpwait0() { asm volatile("cp.async.wait_group 0;\n"); }
__device__ __forceinline__ void cpwait1() { asm volatile("cp.async.wait_group 1;\n"); }

// ---------------- fused weight prep (fp16, transposed) -----------------------
__global__ __launch_bounds__(256)
void prep_weights(const float* __restrict__ w_in, const float* __restrict__ w_out,
                  const float* __restrict__ w_off, const float* __restrict__ b_off,
                  const float* __restrict__ w_mask, const float* __restrict__ b_mask) {
    const int seg = blockIdx.x >> 10;
    const int i = ((blockIdx.x & 1023) << 8) + threadIdx.x;
    if (seg == 0) {
        const int k = i >> 9;
        const int n = i & 511;
        g_winT[n * Cc + k] = __float2half_rn(w_in[i]);
    } else if (seg == 1) {
        const int k = i >> 9;
        const int n = i & 511;
        g_woutT[n * Cc + k] = __float2half_rn(w_out[i]);
    } else {
        const int n = i >> 9;
        const int k = i & 511;
        float v = 0.f;
        if (n < Noff) v = w_off[k * Noff + n];
        else if (n < Ncat) v = w_mask[k * Nmsk + (n - Noff)];
        g_wcatT[i] = __float2half_rn(v);
        if (i < NPAD)
            g_bcat[i] = (i < Noff) ? b_off[i] : (i < Ncat ? b_mask[i - Noff] : 0.f);
    }
}

// ---------------- NCHW -> NHWC transpose (+ fp16 copy) ----------------------
__global__ __launch_bounds__(256)
void nchw_to_nhwc(const float* __restrict__ x) {
    __shared__ float tile[32][33];
    const int bb = blockIdx.z;
    const int hw0 = blockIdx.x * 32;
    const int c0 = blockIdx.y * 32;
    const int tx = threadIdx.x;
    const int ty = threadIdx.y;
    const float* xb = x + (size_t)bb * Cc * HW;
    #pragma unroll
    for (int i = 0; i < 32; i += 8)
        tile[ty + i][tx] = xb[(size_t)(c0 + ty + i) * HW + hw0 + tx];
    __syncthreads();
    #pragma unroll
    for (int i = 0; i < 32; i += 8) {
        const size_t idx = ((size_t)bb * HW + hw0 + ty + i) * Cc + c0 + tx;
        const float v = tile[tx][ty + i];
        g_xh[idx] = v;
        g_xa[idx] = __float2half_rn(v);
    }
}

// ================= fp16 GEMM: BM=128 BN=128 BK=64, 3-stage ==================
// Stage (32768 B): A [0,16K) 128 rows x 128B (64 fp16/row);
//                  B [16K,32K) 128 rows x 128B ([n][k]).
// XOR swizzle: 16B chunk c at row r -> c ^ (r&7). Identical bytes to R14 tf32.
#define HF_STG 32768
#define HF_DSMEM (3 * HF_STG)

__device__ __forceinline__ void hf_fill(const __half* __restrict__ A,
                                        const __half* __restrict__ B,
                                        int bm, int bn, int kt, u32 stg) {
    const int t = threadIdx.x;
    const int row = t >> 1;
    const int cb = (t & 1) * 4;
    const size_t ka = (size_t)(bm + row) * Cc + kt * 64;
    const size_t kb = (size_t)(bn + row) * Cc + kt * 64;
    #pragma unroll
    for (int i = 0; i < 4; i++) {
        const int c = cb + i;
        const u32 d = (u32)(row * 128 + ((c ^ (row & 7)) << 4));
        cpa16(stg + d,         (const void*)(A + ka + c * 8));
        cpa16(stg + 16384 + d, (const void*)(B + kb + c * 8));
    }
    cpcommit();
}

__device__ __forceinline__ void hf_compute(u32 stg, int wm, int wn, int lane,
                                           float acc[4][4][4]) {
    const u32 stgB = stg + 16384;
    const int arow7 = lane & 7;
    const int arow8 = ((lane >> 3) & 1) * 8;
    const int achk = lane >> 4;
    const int brow8 = (lane >> 4) * 8;
    const int bchk = (lane >> 3) & 1;
    #pragma unroll
    for (int ks = 0; ks < 4; ks++) {     // ks = k16 step within 64-K tile
        u32 a[4][4];
        #pragma unroll
        for (int mf = 0; mf < 4; mf++) {
            const int row = wm + mf * 16 + arow7 + arow8;
            const int ch = 2 * ks + achk;
            ldmA4(a[mf], stg + (u32)(row * 128 + ((ch ^ (row & 7)) << 4)));
        }
        u32 b4[2][4];
        #pragma unroll
        for (int j = 0; j < 2; j++) {
            const int row = wn + (2 * j) * 8 + brow8 + arow7;
            const int ch = 2 * ks + bchk;
            ldmB4(b4[j], stgB + (u32)(row * 128 + ((ch ^ (row & 7)) << 4)));
        }
        #pragma unroll
        for (int mf = 0; mf < 4; mf++) {
            #pragma unroll
            for (int j = 0; j < 2; j++) {
                mma_f16(acc[mf][2 * j + 0], a[mf], &b4[j][0]);
                mma_f16(acc[mf][2 * j + 1], a[mf], &b4[j][2]);
            }
        }
    }
}

__device__ __forceinline__ void hf_core(const __half* __restrict__ A,
                                        const __half* __restrict__ B,
                                        int bm, int bn, u32 smbase,
                                        float acc[4][4][4]) {
    const int wid = threadIdx.x >> 5;
    const int lane = threadIdx.x & 31;
    const int wm = (wid & 1) * 64;
    const int wn = (wid >> 1) * 32;
    const u32 st[3] = {smbase, smbase + HF_STG, smbase + 2 * HF_STG};
    hf_fill(A, B, bm, bn, 0, st[0]);
    hf_fill(A, B, bm, bn, 1, st[1]);
    #pragma unroll 1
    for (int kt = 0; kt < 8; kt++) {
        if (kt == 7) cpwait0(); else cpwait1();
        __syncthreads();
        if (kt + 2 < 8) {
            int s2 = kt + 2; s2 -= (s2 / 3) * 3;
            hf_fill(A, B, bm, bn, kt + 2, st[s2]);
        }
        int s = kt; s -= (s / 3) * 3;
        hf_compute(st[s], wm, wn, lane, acc);
    }
}

// ---- GEMM 1 (fp16): xp(fp16) = xa @ winT^T + b_in --------------------------
__global__ __launch_bounds__(256, 2)
void gemm_in(const float* __restrict__ bias) {
    extern __shared__ char smem[];
    const u32 smbase = (u32)__cvta_generic_to_shared(smem);
    float acc[4][4][4];
    #pragma unroll
    for (int i = 0; i < 4; i++)
        #pragma unroll
        for (int j = 0; j < 4; j++)
            #pragma unroll
            for (int q = 0; q < 4; q++) acc[i][j][q] = 0.f;
    const int bm = blockIdx.y * 128;
    const int bn = blockIdx.x * 128;
    hf_core(g_xa, g_winT, bm, bn, smbase, acc);

    const int wid = threadIdx.x >> 5;
    const int lane = threadIdx.x & 31;
    const int wm = (wid & 1) * 64;
    const int wn = (wid >> 1) * 32;
    const int r0 = lane >> 2;
    const int c0 = (lane & 3) * 2;
    #pragma unroll
    for (int mf = 0; mf < 4; mf++) {
        #pragma unroll
        for (int nf = 0; nf < 4; nf++) {
            const int col = bn + wn + nf * 8 + c0;
            #pragma unroll
            for (int half = 0; half < 2; half++) {
                const int row = bm + wm + mf * 16 + r0 + half * 8;
                const float y0 = acc[mf][nf][half * 2 + 0] + bias[col];
                const float y1 = acc[mf][nf][half * 2 + 1] + bias[col + 1];
                *(__half2*)&g_xph[(size_t)row * Cc + col] = __floats2half2_rn(y0, y1);
            }
        }
    }
}

// ---- GEMM 2 (fp16): g_om = x1 @ wcatT^T + bcat  (N=512 pad, store 432) -----
__global__ __launch_bounds__(256, 2)
void gemm_om() {
    extern __shared__ char smem[];
    const u32 smbase = (u32)__cvta_generic_to_shared(smem);
    float acc[4][4][4];
    #pragma unroll
    for (int i = 0; i < 4; i++)
        #pragma unroll
        for (int j = 0; j < 4; j++)
            #pragma unroll
            for (int q = 0; q < 4; q++) acc[i][j][q] = 0.f;
    const int bm = blockIdx.y * 128;
    const int bn = blockIdx.x * 128;
    hf_core(g_x1h, g_wcatT, bm, bn, smbase, acc);

    const int wid = threadIdx.x >> 5;
    const int lane = threadIdx.x & 31;
    const int wm = (wid & 1) * 64;
    const int wn = (wid >> 1) * 32;
    const int r0 = lane >> 2;
    const int c0 = (lane & 3) * 2;
    #pragma unroll
    for (int mf = 0; mf < 4; mf++) {
        #pragma unroll
        for (int nf = 0; nf < 4; nf++) {
            const int col = bn + wn + nf * 8 + c0;
            if (col < Ncat) {
                #pragma unroll
                for (int half = 0; half < 2; half++) {
                    const int row = bm + wm + mf * 16 + r0 + half * 8;
                    float2 v;
                    v.x = acc[mf][nf][half * 2 + 0] + g_bcat[col];
                    v.y = acc[mf][nf][half * 2 + 1] + g_bcat[col + 1];
                    *(float2*)&g_om[(size_t)row * Ncat + col] = v;
                }
            }
        }
    }
}

// ---- GEMM 3 (fp16): out = SiLU(BN(ys @ woutT^T + b_out)) in NCHW -----------
__global__ __launch_bounds__(256, 2)
void gemm_out(const float* __restrict__ bias,
              const float* __restrict__ bn_g, const float* __restrict__ bn_b,
              const float* __restrict__ bn_m, const float* __restrict__ bn_v,
              float* __restrict__ out) {
    extern __shared__ char smem[];
    const u32 smbase = (u32)__cvta_generic_to_shared(smem);
    float acc[4][4][4];
    #pragma unroll
    for (int i = 0; i < 4; i++)
        #pragma unroll
        for (int j = 0; j < 4; j++)
            #pragma unroll
            for (int q = 0; q < 4; q++) acc[i][j][q] = 0.f;
    const int bm = blockIdx.y * 128;
    const int bn = blockIdx.x * 128;
    hf_core(g_ysh, g_woutT, bm, bn, smbase, acc);

    const int wid = threadIdx.x >> 5;
    const int lane = threadIdx.x & 31;
    const int wm = (wid & 1) * 64;
    const int wn = (wid >> 1) * 32;
    const int r0 = lane >> 2;
    const int c0 = (lane & 3) * 2;
    #pragma unroll
    for (int mf = 0; mf < 4; mf++) {
        #pragma unroll
        for (int nf = 0; nf < 4; nf++) {
            const int col = bn + wn + nf * 8 + c0;
            const float s0 = bn_g[col] * rsqrtf(bn_v[col] + 1e-5f);
            const float s1 = bn_g[col + 1] * rsqrtf(bn_v[col + 1] + 1e-5f);
            #pragma unroll
            for (int half = 0; half < 2; half++) {
                const int row = bm + wm + mf * 16 + r0 + half * 8;
                const int bidx = row / HW;
                const int hw = row - bidx * HW;
                float y0 = acc[mf][nf][half * 2 + 0] + bias[col];
                float y1 = acc[mf][nf][half * 2 + 1] + bias[col + 1];
                y0 = (y0 - bn_m[col]) * s0 + bn_b[col];
                y1 = (y1 - bn_m[col + 1]) * s1 + bn_b[col + 1];
                out[((size_t)bidx * Cc + col) * HW + hw]     = y0 / (1.0f + expf(-y0));
                out[((size_t)bidx * Cc + col + 1) * HW + hw] = y1 / (1.0f + expf(-y1));
            }
        }
    }
}

// ------- depthwise 3x3 + LN + GELU: 8-pixel sliding window per block -------
__global__ __launch_bounds__(256)
void dw_ln_gelu(const float* __restrict__ wdw, const float* __restrict__ bdw,
                const float* __restrict__ lng, const float* __restrict__ lnb) {
    __shared__ float sA[8][8];
    __shared__ float sB[8][8];
    const int m0 = blockIdx.x * 8;
    const int b = m0 / HW;
    const int hw0 = m0 - b * HW;
    const int h = hw0 / Ww;
    const int w0 = hw0 - h * Ww;
    const int tid = threadIdx.x;
    const int wid = tid >> 5;
    const int lane = tid & 31;
    const int c = tid * 2;

    float a0[8], a1[8];
    #pragma unroll
    for (int i = 0; i < 8; i++) { a0[i] = 0.f; a1[i] = 0.f; }

    #pragma unroll
    for (int ky = 0; ky < 3; ky++) {
        const int hy = h + ky - 1;
        if ((unsigned)hy >= (unsigned)Hh) continue;
        const float2 wv0 = *(const float2*)&wdw[(ky * 3 + 0) * Cc + c];
        const float2 wv1 = *(const float2*)&wdw[(ky * 3 + 1) * Cc + c];
        const float2 wv2 = *(const float2*)&wdw[(ky * 3 + 2) * Cc + c];
        float2 rv[10];
        #pragma unroll
        for (int j = 0; j < 10; j++) {
            const int wx = w0 + j - 1;
            if ((unsigned)wx < (unsigned)Ww)
                rv[j] = *(const float2*)&g_xh[((size_t)(b * HW + hy * Ww + wx)) * Cc + c];
            else
                rv[j] = make_float2(0.f, 0.f);
        }
        #pragma unroll
        for (int px = 0; px < 8; px++) {
            a0[px] = fmaf(rv[px].x,     wv0.x, a0[px]);
            a1[px] = fmaf(rv[px].y,     wv0.y, a1[px]);
            a0[px] = fmaf(rv[px + 1].x, wv1.x, a0[px]);
            a1[px] = fmaf(rv[px + 1].y, wv1.y, a1[px]);
            a0[px] = fmaf(rv[px + 2].x, wv2.x, a0[px]);
            a1[px] = fmaf(rv[px + 2].y, wv2.y, a1[px]);
        }
    }
    const float2 bb2 = *(const float2*)&bdw[c];
    #pragma unroll
    for (int px = 0; px < 8; px++) { a0[px] += bb2.x; a1[px] += bb2.y; }

    #pragma unroll
    for (int px = 0; px < 8; px++) {
        float part = a0[px] + a1[px];
        #pragma unroll
        for (int s = 16; s > 0; s >>= 1) part += __shfl_xor_sync(0xffffffffu, part, s);
        if (lane == 0) sA[wid][px] = part;
    }
    __syncthreads();
    float mu[8];
    #pragma unroll
    for (int px = 0; px < 8; px++) {
        float s = 0.f;
        #pragma unroll
        for (int i = 0; i < 8; i++) s += sA[i][px];
        mu[px] = s * (1.0f / 512.0f);
    }
    #pragma unroll
    for (int px = 0; px < 8; px++) {
        const float d0 = a0[px] - mu[px];
        const float d1 = a1[px] - mu[px];
        float vp = d0 * d0 + d1 * d1;
        #pragma unroll
        for (int s = 16; s > 0; s >>= 1) vp += __shfl_xor_sync(0xffffffffu, vp, s);
        if (lane == 0) sB[wid][px] = vp;
    }
    __syncthreads();

    const float2 gg = *(const float2*)&lng[c];
    const float2 be = *(const float2*)&lnb[c];
    #pragma unroll
    for (int px = 0; px < 8; px++) {
        float var = 0.f;
        #pragma unroll
        for (int i = 0; i < 8; i++) var += sB[i][px];
        var *= (1.0f / 512.0f);
        const float rstd = rsqrtf(var + 1e-6f);
        float o0 = (a0[px] - mu[px]) * rstd * gg.x + be.x;
        float o1 = (a1[px] - mu[px]) * rstd * gg.y + be.y;
        o0 = 0.5f * o0 * (1.0f + erff(o0 * 0.7071067811865475f));
        o1 = 0.5f * o1 * (1.0f + erff(o1 * 0.7071067811865475f));
        *(__half2*)&g_x1h[(size_t)(m0 + px) * Cc + c] = __floats2half2_rn(o0, o1);
    }
}

// ------- DCNv3 sampling + fused softmax: warp = (pixel, group-pair) --------
__global__ __launch_bounds__(256)
void dcn_sample() {
    const int wuid = blockIdx.x * 8 + (threadIdx.x >> 5);
    const int lane = threadIdx.x & 31;
    if (wuid >= Mtot * (Gg / 2)) return;
    const int m = wuid >> 3;
    const int gp = wuid & 7;
    const int g = gp * 2 + (lane >> 4);
    const int ch = (lane & 15) * 2;
    const int b = m / HW;
    const int hw = m - b * HW;
    const int h = hw / Ww;
    const int w = hw - h * Ww;

    const float* offp = g_om + (size_t)m * Ncat + g * (Pp * 2);
    const float* mskp = g_om + (size_t)m * Ncat + Noff + g * Pp;
    const __half* base = g_xph + (size_t)b * HW * Cc + g * GC + ch;

    float logit[Pp];
    float mx = -1e30f;
    #pragma unroll
    for (int p = 0; p < Pp; p++) { logit[p] = mskp[p]; mx = fmaxf(mx, logit[p]); }
    float ssum = 0.f;
    #pragma unroll
    for (int p = 0; p < Pp; p++) { logit[p] = expf(logit[p] - mx); ssum += logit[p]; }
    const float sinv = 1.0f / ssum;

    float acc0 = 0.f, acc1 = 0.f;
    #pragma unroll
    for (int p = 0; p < Pp; p++) {
        const int kx = p / 3;
        const int ky = p - kx * 3;
        const float2 o2 = *(const float2*)&offp[2 * p];
        const float fx = (float)(w + kx - 1) + o2.x;
        const float fy = (float)(h + ky - 1) + o2.y;
        const float x0f = floorf(fx);
        const float y0f = floorf(fy);
        const float txf = fx - x0f;
        const float tyf = fy - y0f;
        const int x0 = (int)x0f;
        const int y0 = (int)y0f;
        const float msk = logit[p] * sinv;
        float2 v00 = make_float2(0.f, 0.f), v01 = v00, v10 = v00, v11 = v00;
        const bool yi0 = (unsigned)y0 < (unsigned)Hh;
        const bool yi1 = (unsigned)(y0 + 1) < (unsigned)Hh;
        const bool xi0 = (unsigned)x0 < (unsigned)Ww;
        const bool xi1 = (unsigned)(x0 + 1) < (unsigned)Ww;
        if (yi0 && xi0) v00 = __half22float2(*(const __half2*)&base[(size_t)(y0 * Ww + x0) * Cc]);
        if (yi0 && xi1) v01 = __half22float2(*(const __half2*)&base[(size_t)(y0 * Ww + x0 + 1) * Cc]);
        if (yi1 && xi0) v10 = __half22float2(*(const __half2*)&base[(size_t)((y0 + 1) * Ww + x0) * Cc]);
        if (yi1 && xi1) v11 = __half22float2(*(const __half2*)&base[(size_t)((y0 + 1) * Ww + x0 + 1) * Cc]);
        const float w00 = (1.f - tyf) * (1.f - txf);
        const float w01 = (1.f - tyf) * txf;
        const float w10 = tyf * (1.f - txf);
        const float w11 = tyf * txf;
        const float s0 = w00 * v00.x + w01 * v01.x + w10 * v10.x + w11 * v11.x;
        const float s1 = w00 * v00.y + w01 * v01.y + w10 * v10.y + w11 * v11.y;
        acc0 = fmaf(msk, s0, acc0);
        acc1 = fmaf(msk, s1, acc1);
    }
    *(__half2*)&g_ysh[(size_t)m * Cc + g * GC + ch] = __floats2half2_rn(acc0, acc1);
}

// ---------------- host launch ----------------------------------------------
extern "C" void kernel_launch(void* const* d_in, const int* in_sizes, int n_in,
                              void* d_out, int out_size) {
    const float* x      = (const float*)d_in[0];
    const float* w_in   = (const float*)d_in[1];
    const float* b_in   = (const float*)d_in[2];
    const float* w_dw   = (const float*)d_in[3];
    const float* b_dw   = (const float*)d_in[4];
    const float* ln_g   = (const float*)d_in[5];
    const float* ln_b   = (const float*)d_in[6];
    const float* w_off  = (const float*)d_in[7];
    const float* b_off  = (const float*)d_in[8];
    const float* w_mask = (const float*)d_in[9];
    const float* b_mask = (const float*)d_in[10];
    const float* w_out  = (const float*)d_in[11];
    const float* b_out  = (const float*)d_in[12];
    const float* bn_g   = (const float*)d_in[13];
    const float* bn_b   = (const float*)d_in[14];
    const float* bn_m   = (const float*)d_in[15];
    const float* bn_v   = (const float*)d_in[16];

    // one-time setup (first call is the uncaptured correctness run)
    static int inited = 0;
    static cudaStream_t s1;
    static cudaEvent_t evS, evT, evP, ev2;
    if (!inited) {
        cudaFuncSetAttribute(gemm_in, cudaFuncAttributeMaxDynamicSharedMemorySize, HF_DSMEM);
        cudaFuncSetAttribute(gemm_om, cudaFuncAttributeMaxDynamicSharedMemorySize, HF_DSMEM);
        cudaFuncSetAttribute(gemm_out, cudaFuncAttributeMaxDynamicSharedMemorySize, HF_DSMEM);
        cudaStreamCreateWithFlags(&s1, cudaStreamNonBlocking);
        cudaEventCreateWithFlags(&evS, cudaEventDisableTiming);
        cudaEventCreateWithFlags(&evT, cudaEventDisableTiming);
        cudaEventCreateWithFlags(&evP, cudaEventDisableTiming);
        cudaEventCreateWithFlags(&ev2, cudaEventDisableTiming);
        inited = 1;
    }

    // fork s1 from the main (capture) stream
    cudaEventRecord(evS, 0);
    cudaStreamWaitEvent(s1, evS, 0);

    // s1: fused weight prep
    prep_weights<<<3072, 256, 0, s1>>>(w_in, w_out, w_off, b_off, w_mask, b_mask);
    cudaEventRecord(evP, s1);

    // s0: NCHW -> NHWC (+ fp16 copy)
    nchw_to_nhwc<<<dim3(HW / 32, Cc / 32, Bn), dim3(32, 8)>>>(x);
    cudaEventRecord(evT, 0);

    // s1: depthwise branch + offset/mask GEMM (after transpose)
    cudaStreamWaitEvent(s1, evT, 0);
    dw_ln_gelu<<<Mtot / 8, 256, 0, s1>>>(w_dw, b_dw, ln_g, ln_b);
    gemm_om<<<dim3(NPAD / 128, Mtot / 128), 256, HF_DSMEM, s1>>>();
    cudaEventRecord(ev2, s1);

    // s0: input_proj — overlaps with dw+gemm_om on s1
    cudaStreamWaitEvent(0, evP, 0);
    gemm_in<<<dim3(Cc / 128, Mtot / 128), 256, HF_DSMEM>>>(b_in);

    // join: dcn needs xp (s0) + om (s1)
    cudaStreamWaitEvent(0, ev2, 0);
    dcn_sample<<<(Mtot * (Gg / 2)) / 8, 256>>>();
    // output_proj + BN + SiLU (fp16 MMA)
    gemm_out<<<dim3(Cc / 128, Mtot / 128), 256, HF_DSMEM>>>(b_out, bn_g, bn_b,
                                                            bn_m, bn_v, (float*)d_out);
}

// round 16
// speedup vs baseline: 1.8312x; 1.1490x over previous
#include <cuda_runtime.h>
#include <cuda_bf16.h>
#include <cuda_fp16.h>
#include <math.h>
#include <cstdint>

typedef unsigned int u32;
typedef unsigned short u16;
typedef unsigned long long u64;

// Problem constants
#define Bn 4
#define Cc 512
#define Hh 56
#define Ww 56
#define Gg 16
#define Pp 9
#define GC 32
#define HW 3136          // 56*56
#define Mtot 12544       // B*H*W
#define Noff 288         // G*P*2
#define Nmsk 144         // G*P
#define Ncat 432         // Noff+Nmsk
#define NPAD 512         // Ncat padded to 128 multiple

// ---------------- scratch (device globals; no allocation allowed) ----------
__device__ __half g_xa[Mtot * Cc];        // fp16 NHWC (GEMM1 A + depthwise in)
__device__ __half g_xph[Mtot * Cc];       // input_proj output fp16 (dcn only)
__device__ __half g_x1h[Mtot * Cc];       // dw+LN+GELU fp16 (GEMM2 A)
__device__ float  g_om[Mtot * Ncat];      // [offset|mask logits]
__device__ __half g_ysh[Mtot * Cc];       // DCN output fp16 (GEMM3 A)
__device__ __half g_winT[Cc * Cc];        // w_in^T fp16: [n][k]
__device__ __half g_wcatT[NPAD * Cc];     // concat weight^T fp16: [n][k]
__device__ __half g_woutT[Cc * Cc];       // w_out^T fp16: [n][k]
__device__ float  g_bcat[NPAD];

// ---------------- helpers ---------------------------------------------------
__device__ __forceinline__ void ldmA4(u32* r, u32 addr) {
    asm volatile("ldmatrix.sync.aligned.m8n8.x4.shared.b16 {%0,%1,%2,%3}, [%4];\n"
                 : "=r"(r[0]), "=r"(r[1]), "=r"(r[2]), "=r"(r[3]) : "r"(addr));
}
__device__ __forceinline__ void ldmB4(u32* r, u32 addr) {
    asm volatile("ldmatrix.sync.aligned.m8n8.x4.shared.b16 {%0,%1,%2,%3}, [%4];\n"
                 : "=r"(r[0]), "=r"(r[1]), "=r"(r[2]), "=r"(r[3]) : "r"(addr));
}
__device__ __forceinline__ void mma_f16(float* c, const u32* a, const u32* b) {
    asm volatile("mma.sync.aligned.m16n8k16.row.col.f32.f16.f16.f32 "
                 "{%0,%1,%2,%3}, {%4,%5,%6,%7}, {%8,%9}, {%0,%1,%2,%3};\n"
                 : "+f"(c[0]), "+f"(c[1]), "+f"(c[2]), "+f"(c[3])
                 : "r"(a[0]), "r"(a[1]), "r"(a[2]), "r"(a[3]), "r"(b[0]), "r"(b[1]));
}
__device__ __forceinline__ void cpa16(u32 dst, const void* src) {
    asm volatile("cp.async.cg.shared.global [%0], [%1], 16;\n" :: "r"(dst), "l"(src));
}
__device__ __forceinline__ void cpcommit() { asm volatile("cp.async.commit_group;\n"); }
__device__ __forceinline__ void cpwait0() { asm volatile("cp.async.wait_group 0;\n"); }
__device__ __forceinline__ void cpwait1() { asm volatile("cp.async.wait_group 1;\n"); }

// ---------------- fused weight prep (fp16, transposed) -----------------------
__global__ __launch_bounds__(256)
void prep_weights(const float* __restrict__ w_in, const float* __restrict__ w_out,
                  const float* __restrict__ w_off, const float* __restrict__ b_off,
                  const float* __restrict__ w_mask, const float* __restrict__ b_mask) {
    const int seg = blockIdx.x >> 10;
    const int i = ((blockIdx.x & 1023) << 8) + threadIdx.x;
    if (seg == 0) {
        const int k = i >> 9;
        const int n = i & 511;
        g_winT[n * Cc + k] = __float2half_rn(w_in[i]);
    } else if (seg == 1) {
        const int k = i >> 9;
        const int n = i & 511;
        g_woutT[n * Cc + k] = __float2half_rn(w_out[i]);
    } else {
        const int n = i >> 9;
        const int k = i & 511;
        float v = 0.f;
        if (n < Noff) v = w_off[k * Noff + n];
        else if (n < Ncat) v = w_mask[k * Nmsk + (n - Noff)];
        g_wcatT[i] = __float2half_rn(v);
        if (i < NPAD)
            g_bcat[i] = (i < Noff) ? b_off[i] : (i < Ncat ? b_mask[i - Noff] : 0.f);
    }
}

// ---------------- NCHW -> NHWC transpose (fp16 out only) --------------------
__global__ __launch_bounds__(256)
void nchw_to_nhwc(const float* __restrict__ x) {
    __shared__ float tile[32][33];
    const int bb = blockIdx.z;
    const int hw0 = blockIdx.x * 32;
    const int c0 = blockIdx.y * 32;
    const int tx = threadIdx.x;
    const int ty = threadIdx.y;
    const float* xb = x + (size_t)bb * Cc * HW;
    #pragma unroll
    for (int i = 0; i < 32; i += 8)
        tile[ty + i][tx] = xb[(size_t)(c0 + ty + i) * HW + hw0 + tx];
    __syncthreads();
    #pragma unroll
    for (int i = 0; i < 32; i += 8) {
        const size_t idx = ((size_t)bb * HW + hw0 + ty + i) * Cc + c0 + tx;
        g_xa[idx] = __float2half_rn(tile[tx][ty + i]);
    }
}

// ================= fp16 GEMM: BM=128 BN=128 BK=64, 3-stage ==================
#define HF_STG 32768
#define HF_DSMEM (3 * HF_STG)

__device__ __forceinline__ void hf_fill(const __half* __restrict__ A,
                                        const __half* __restrict__ B,
                                        int bm, int bn, int kt, u32 stg) {
    const int t = threadIdx.x;
    const int row = t >> 1;
    const int cb = (t & 1) * 4;
    const size_t ka = (size_t)(bm + row) * Cc + kt * 64;
    const size_t kb = (size_t)(bn + row) * Cc + kt * 64;
    #pragma unroll
    for (int i = 0; i < 4; i++) {
        const int c = cb + i;
        const u32 d = (u32)(row * 128 + ((c ^ (row & 7)) << 4));
        cpa16(stg + d,         (const void*)(A + ka + c * 8));
        cpa16(stg + 16384 + d, (const void*)(B + kb + c * 8));
    }
    cpcommit();
}

__device__ __forceinline__ void hf_compute(u32 stg, int wm, int wn, int lane,
                                           float acc[4][4][4]) {
    const u32 stgB = stg + 16384;
    const int arow7 = lane & 7;
    const int arow8 = ((lane >> 3) & 1) * 8;
    const int achk = lane >> 4;
    const int brow8 = (lane >> 4) * 8;
    const int bchk = (lane >> 3) & 1;
    #pragma unroll
    for (int ks = 0; ks < 4; ks++) {
        u32 a[4][4];
        #pragma unroll
        for (int mf = 0; mf < 4; mf++) {
            const int row = wm + mf * 16 + arow7 + arow8;
            const int ch = 2 * ks + achk;
            ldmA4(a[mf], stg + (u32)(row * 128 + ((ch ^ (row & 7)) << 4)));
        }
        u32 b4[2][4];
        #pragma unroll
        for (int j = 0; j < 2; j++) {
            const int row = wn + (2 * j) * 8 + brow8 + arow7;
            const int ch = 2 * ks + bchk;
            ldmB4(b4[j], stgB + (u32)(row * 128 + ((ch ^ (row & 7)) << 4)));
        }
        #pragma unroll
        for (int mf = 0; mf < 4; mf++) {
            #pragma unroll
            for (int j = 0; j < 2; j++) {
                mma_f16(acc[mf][2 * j + 0], a[mf], &b4[j][0]);
                mma_f16(acc[mf][2 * j + 1], a[mf], &b4[j][2]);
            }
        }
    }
}

__device__ __forceinline__ void hf_core(const __half* __restrict__ A,
                                        const __half* __restrict__ B,
                                        int bm, int bn, u32 smbase,
                                        float acc[4][4][4]) {
    const int wid = threadIdx.x >> 5;
    const int lane = threadIdx.x & 31;
    const int wm = (wid & 1) * 64;
    const int wn = (wid >> 1) * 32;
    const u32 st[3] = {smbase, smbase + HF_STG, smbase + 2 * HF_STG};
    hf_fill(A, B, bm, bn, 0, st[0]);
    hf_fill(A, B, bm, bn, 1, st[1]);
    #pragma unroll 1
    for (int kt = 0; kt < 8; kt++) {
        if (kt == 7) cpwait0(); else cpwait1();
        __syncthreads();
        if (kt + 2 < 8) {
            int s2 = kt + 2; s2 -= (s2 / 3) * 3;
            hf_fill(A, B, bm, bn, kt + 2, st[s2]);
        }
        int s = kt; s -= (s / 3) * 3;
        hf_compute(st[s], wm, wn, lane, acc);
    }
}

// ---- GEMM 1 (fp16): xp(fp16) = xa @ winT^T + b_in --------------------------
__global__ __launch_bounds__(256, 2)
void gemm_in(const float* __restrict__ bias) {
    extern __shared__ char smem[];
    const u32 smbase = (u32)__cvta_generic_to_shared(smem);
    float acc[4][4][4];
    #pragma unroll
    for (int i = 0; i < 4; i++)
        #pragma unroll
        for (int j = 0; j < 4; j++)
            #pragma unroll
            for (int q = 0; q < 4; q++) acc[i][j][q] = 0.f;
    const int bm = blockIdx.y * 128;
    const int bn = blockIdx.x * 128;
    hf_core(g_xa, g_winT, bm, bn, smbase, acc);

    const int wid = threadIdx.x >> 5;
    const int lane = threadIdx.x & 31;
    const int wm = (wid & 1) * 64;
    const int wn = (wid >> 1) * 32;
    const int r0 = lane >> 2;
    const int c0 = (lane & 3) * 2;
    #pragma unroll
    for (int mf = 0; mf < 4; mf++) {
        #pragma unroll
        for (int nf = 0; nf < 4; nf++) {
            const int col = bn + wn + nf * 8 + c0;
            #pragma unroll
            for (int half = 0; half < 2; half++) {
                const int row = bm + wm + mf * 16 + r0 + half * 8;
                const float y0 = acc[mf][nf][half * 2 + 0] + bias[col];
                const float y1 = acc[mf][nf][half * 2 + 1] + bias[col + 1];
                *(__half2*)&g_xph[(size_t)row * Cc + col] = __floats2half2_rn(y0, y1);
            }
        }
    }
}

// ---- GEMM 2 (fp16): g_om = x1 @ wcatT^T + bcat  (N=512 pad, store 432) -----
__global__ __launch_bounds__(256, 2)
void gemm_om() {
    extern __shared__ char smem[];
    const u32 smbase = (u32)__cvta_generic_to_shared(smem);
    float acc[4][4][4];
    #pragma unroll
    for (int i = 0; i < 4; i++)
        #pragma unroll
        for (int j = 0; j < 4; j++)
            #pragma unroll
            for (int q = 0; q < 4; q++) acc[i][j][q] = 0.f;
    const int bm = blockIdx.y * 128;
    const int bn = blockIdx.x * 128;
    hf_core(g_x1h, g_wcatT, bm, bn, smbase, acc);

    const int wid = threadIdx.x >> 5;
    const int lane = threadIdx.x & 31;
    const int wm = (wid & 1) * 64;
    const int wn = (wid >> 1) * 32;
    const int r0 = lane >> 2;
    const int c0 = (lane & 3) * 2;
    #pragma unroll
    for (int mf = 0; mf < 4; mf++) {
        #pragma unroll
        for (int nf = 0; nf < 4; nf++) {
            const int col = bn + wn + nf * 8 + c0;
            if (col < Ncat) {
                #pragma unroll
                for (int half = 0; half < 2; half++) {
                    const int row = bm + wm + mf * 16 + r0 + half * 8;
                    float2 v;
                    v.x = acc[mf][nf][half * 2 + 0] + g_bcat[col];
                    v.y = acc[mf][nf][half * 2 + 1] + g_bcat[col + 1];
                    *(float2*)&g_om[(size_t)row * Ncat + col] = v;
                }
            }
        }
    }
}

// ---- GEMM 3 (fp16): out = SiLU(BN(ys @ woutT^T + b_out)) in NCHW -----------
__global__ __launch_bounds__(256, 2)
void gemm_out(const float* __restrict__ bias,
              const float* __restrict__ bn_g, const float* __restrict__ bn_b,
              const float* __restrict__ bn_m, const float* __restrict__ bn_v,
              float* __restrict__ out) {
    extern __shared__ char smem[];
    const u32 smbase = (u32)__cvta_generic_to_shared(smem);
    float acc[4][4][4];
    #pragma unroll
    for (int i = 0; i < 4; i++)
        #pragma unroll
        for (int j = 0; j < 4; j++)
            #pragma unroll
            for (int q = 0; q < 4; q++) acc[i][j][q] = 0.f;
    const int bm = blockIdx.y * 128;
    const int bn = blockIdx.x * 128;
    hf_core(g_ysh, g_woutT, bm, bn, smbase, acc);

    const int wid = threadIdx.x >> 5;
    const int lane = threadIdx.x & 31;
    const int wm = (wid & 1) * 64;
    const int wn = (wid >> 1) * 32;
    const int r0 = lane >> 2;
    const int c0 = (lane & 3) * 2;
    #pragma unroll
    for (int mf = 0; mf < 4; mf++) {
        #pragma unroll
        for (int nf = 0; nf < 4; nf++) {
            const int col = bn + wn + nf * 8 + c0;
            const float s0 = bn_g[col] * rsqrtf(bn_v[col] + 1e-5f);
            const float s1 = bn_g[col + 1] * rsqrtf(bn_v[col + 1] + 1e-5f);
            #pragma unroll
            for (int half = 0; half < 2; half++) {
                const int row = bm + wm + mf * 16 + r0 + half * 8;
                const int bidx = row / HW;
                const int hw = row - bidx * HW;
                float y0 = acc[mf][nf][half * 2 + 0] + bias[col];
                float y1 = acc[mf][nf][half * 2 + 1] + bias[col + 1];
                y0 = (y0 - bn_m[col]) * s0 + bn_b[col];
                y1 = (y1 - bn_m[col + 1]) * s1 + bn_b[col + 1];
                out[((size_t)bidx * Cc + col) * HW + hw]     = y0 / (1.0f + expf(-y0));
                out[((size_t)bidx * Cc + col + 1) * HW + hw] = y1 / (1.0f + expf(-y1));
            }
        }
    }
}

// ------- depthwise 3x3 + LN + GELU: 8-pixel sliding window, fp16 in --------
__global__ __launch_bounds__(256)
void dw_ln_gelu(const float* __restrict__ wdw, const float* __restrict__ bdw,
                const float* __restrict__ lng, const float* __restrict__ lnb) {
    __shared__ float sA[8][8];
    __shared__ float sB[8][8];
    const int m0 = blockIdx.x * 8;
    const int b = m0 / HW;
    const int hw0 = m0 - b * HW;
    const int h = hw0 / Ww;
    const int w0 = hw0 - h * Ww;
    const int tid = threadIdx.x;
    const int wid = tid >> 5;
    const int lane = tid & 31;
    const int c = tid * 2;

    float a0[8], a1[8];
    #pragma unroll
    for (int i = 0; i < 8; i++) { a0[i] = 0.f; a1[i] = 0.f; }

    #pragma unroll
    for (int ky = 0; ky < 3; ky++) {
        const int hy = h + ky - 1;
        if ((unsigned)hy >= (unsigned)Hh) continue;
        const float2 wv0 = *(const float2*)&wdw[(ky * 3 + 0) * Cc + c];
        const float2 wv1 = *(const float2*)&wdw[(ky * 3 + 1) * Cc + c];
        const float2 wv2 = *(const float2*)&wdw[(ky * 3 + 2) * Cc + c];
        float2 rv[10];
        #pragma unroll
        for (int j = 0; j < 10; j++) {
            const int wx = w0 + j - 1;
            if ((unsigned)wx < (unsigned)Ww)
                rv[j] = __half22float2(
                    *(const __half2*)&g_xa[((size_t)(b * HW + hy * Ww + wx)) * Cc + c]);
            else
                rv[j] = make_float2(0.f, 0.f);
        }
        #pragma unroll
        for (int px = 0; px < 8; px++) {
            a0[px] = fmaf(rv[px].x,     wv0.x, a0[px]);
            a1[px] = fmaf(rv[px].y,     wv0.y, a1[px]);
            a0[px] = fmaf(rv[px + 1].x, wv1.x, a0[px]);
            a1[px] = fmaf(rv[px + 1].y, wv1.y, a1[px]);
            a0[px] = fmaf(rv[px + 2].x, wv2.x, a0[px]);
            a1[px] = fmaf(rv[px + 2].y, wv2.y, a1[px]);
        }
    }
    const float2 bb2 = *(const float2*)&bdw[c];
    #pragma unroll
    for (int px = 0; px < 8; px++) { a0[px] += bb2.x; a1[px] += bb2.y; }

    #pragma unroll
    for (int px = 0; px < 8; px++) {
        float part = a0[px] + a1[px];
        #pragma unroll
        for (int s = 16; s > 0; s >>= 1) part += __shfl_xor_sync(0xffffffffu, part, s);
        if (lane == 0) sA[wid][px] = part;
    }
    __syncthreads();
    float mu[8];
    #pragma unroll
    for (int px = 0; px < 8; px++) {
        float s = 0.f;
        #pragma unroll
        for (int i = 0; i < 8; i++) s += sA[i][px];
        mu[px] = s * (1.0f / 512.0f);
    }
    #pragma unroll
    for (int px = 0; px < 8; px++) {
        const float d0 = a0[px] - mu[px];
        const float d1 = a1[px] - mu[px];
        float vp = d0 * d0 + d1 * d1;
        #pragma unroll
        for (int s = 16; s > 0; s >>= 1) vp += __shfl_xor_sync(0xffffffffu, vp, s);
        if (lane == 0) sB[wid][px] = vp;
    }
    __syncthreads();

    const float2 gg = *(const float2*)&lng[c];
    const float2 be = *(const float2*)&lnb[c];
    #pragma unroll
    for (int px = 0; px < 8; px++) {
        float var = 0.f;
        #pragma unroll
        for (int i = 0; i < 8; i++) var += sB[i][px];
        var *= (1.0f / 512.0f);
        const float rstd = rsqrtf(var + 1e-6f);
        float o0 = (a0[px] - mu[px]) * rstd * gg.x + be.x;
        float o1 = (a1[px] - mu[px]) * rstd * gg.y + be.y;
        o0 = 0.5f * o0 * (1.0f + erff(o0 * 0.7071067811865475f));
        o1 = 0.5f * o1 * (1.0f + erff(o1 * 0.7071067811865475f));
        *(__half2*)&g_x1h[(size_t)(m0 + px) * Cc + c] = __floats2half2_rn(o0, o1);
    }
}

// ------- DCNv3 sampling + fused softmax: warp = (pixel, group-quad) --------
// Lanes [8q..8q+7] serve group 4*gq+q; each lane handles 4 fp16 channels.
__global__ __launch_bounds__(256)
void dcn_sample() {
    const int wuid = blockIdx.x * 8 + (threadIdx.x >> 5);
    const int lane = threadIdx.x & 31;
    if (wuid >= Mtot * (Gg / 4)) return;
    const int m = wuid >> 2;              // Gg/4 = 4 quads
    const int gq = wuid & 3;
    const int g = gq * 4 + (lane >> 3);
    const int ch = (lane & 7) * 4;
    const int b = m / HW;
    const int hw = m - b * HW;
    const int h = hw / Ww;
    const int w = hw - h * Ww;

    const float* offp = g_om + (size_t)m * Ncat + g * (Pp * 2);
    const float* mskp = g_om + (size_t)m * Ncat + Noff + g * Pp;
    const __half* base = g_xph + (size_t)b * HW * Cc + g * GC + ch;

    float logit[Pp];
    float mx = -1e30f;
    #pragma unroll
    for (int p = 0; p < Pp; p++) { logit[p] = mskp[p]; mx = fmaxf(mx, logit[p]); }
    float ssum = 0.f;
    #pragma unroll
    for (int p = 0; p < Pp; p++) { logit[p] = expf(logit[p] - mx); ssum += logit[p]; }
    const float sinv = 1.0f / ssum;

    float acc0 = 0.f, acc1 = 0.f, acc2 = 0.f, acc3 = 0.f;
    #pragma unroll
    for (int p = 0; p < Pp; p++) {
        const int kx = p / 3;
        const int ky = p - kx * 3;
        const float2 o2 = *(const float2*)&offp[2 * p];
        const float fx = (float)(w + kx - 1) + o2.x;
        const float fy = (float)(h + ky - 1) + o2.y;
        const float x0f = floorf(fx);
        const float y0f = floorf(fy);
        const float txf = fx - x0f;
        const float tyf = fy - y0f;
        const int x0 = (int)x0f;
        const int y0 = (int)y0f;
        const float msk = logit[p] * sinv;
        float4 v00 = make_float4(0.f, 0.f, 0.f, 0.f);
        float4 v01 = v00, v10 = v00, v11 = v00;
        const bool yi0 = (unsigned)y0 < (unsigned)Hh;
        const bool yi1 = (unsigned)(y0 + 1) < (unsigned)Hh;
        const bool xi0 = (unsigned)x0 < (unsigned)Ww;
        const bool xi1 = (unsigned)(x0 + 1) < (unsigned)Ww;
        if (yi0 && xi0) {
            const __half2* q = (const __half2*)&base[(size_t)(y0 * Ww + x0) * Cc];
            const float2 lo = __half22float2(q[0]), hi = __half22float2(q[1]);
            v00 = make_float4(lo.x, lo.y, hi.x, hi.y);
        }
        if (yi0 && xi1) {
            const __half2* q = (const __half2*)&base[(size_t)(y0 * Ww + x0 + 1) * Cc];
            const float2 lo = __half22float2(q[0]), hi = __half22float2(q[1]);
            v01 = make_float4(lo.x, lo.y, hi.x, hi.y);
        }
        if (yi1 && xi0) {
            const __half2* q = (const __half2*)&base[(size_t)((y0 + 1) * Ww + x0) * Cc];
            const float2 lo = __half22float2(q[0]), hi = __half22float2(q[1]);
            v10 = make_float4(lo.x, lo.y, hi.x, hi.y);
        }
        if (yi1 && xi1) {
            const __half2* q = (const __half2*)&base[(size_t)((y0 + 1) * Ww + x0 + 1) * Cc];
            const float2 lo = __half22float2(q[0]), hi = __half22float2(q[1]);
            v11 = make_float4(lo.x, lo.y, hi.x, hi.y);
        }
        const float w00 = (1.f - tyf) * (1.f - txf);
        const float w01 = (1.f - tyf) * txf;
        const float w10 = tyf * (1.f - txf);
        const float w11 = tyf * txf;
        acc0 = fmaf(msk, w00 * v00.x + w01 * v01.x + w10 * v10.x + w11 * v11.x, acc0);
        acc1 = fmaf(msk, w00 * v00.y + w01 * v01.y + w10 * v10.y + w11 * v11.y, acc1);
        acc2 = fmaf(msk, w00 * v00.z + w01 * v01.z + w10 * v10.z + w11 * v11.z, acc2);
        acc3 = fmaf(msk, w00 * v00.w + w01 * v01.w + w10 * v10.w + w11 * v11.w, acc3);
    }
    __half2* dst = (__half2*)&g_ysh[(size_t)m * Cc + g * GC + ch];
    dst[0] = __floats2half2_rn(acc0, acc1);
    dst[1] = __floats2half2_rn(acc2, acc3);
}

// ---------------- host launch ----------------------------------------------
extern "C" void kernel_launch(void* const* d_in, const int* in_sizes, int n_in,
                              void* d_out, int out_size) {
    const float* x      = (const float*)d_in[0];
    const float* w_in   = (const float*)d_in[1];
    const float* b_in   = (const float*)d_in[2];
    const float* w_dw   = (const float*)d_in[3];
    const float* b_dw   = (const float*)d_in[4];
    const float* ln_g   = (const float*)d_in[5];
    const float* ln_b   = (const float*)d_in[6];
    const float* w_off  = (const float*)d_in[7];
    const float* b_off  = (const float*)d_in[8];
    const float* w_mask = (const float*)d_in[9];
    const float* b_mask = (const float*)d_in[10];
    const float* w_out  = (const float*)d_in[11];
    const float* b_out  = (const float*)d_in[12];
    const float* bn_g   = (const float*)d_in[13];
    const float* bn_b   = (const float*)d_in[14];
    const float* bn_m   = (const float*)d_in[15];
    const float* bn_v   = (const float*)d_in[16];

    // one-time setup (first call is the uncaptured correctness run)
    static int inited = 0;
    static cudaStream_t s1;
    static cudaEvent_t evS, evT, evP, ev2;
    if (!inited) {
        cudaFuncSetAttribute(gemm_in, cudaFuncAttributeMaxDynamicSharedMemorySize, HF_DSMEM);
        cudaFuncSetAttribute(gemm_om, cudaFuncAttributeMaxDynamicSharedMemorySize, HF_DSMEM);
        cudaFuncSetAttribute(gemm_out, cudaFuncAttributeMaxDynamicSharedMemorySize, HF_DSMEM);
        cudaStreamCreateWithFlags(&s1, cudaStreamNonBlocking);
        cudaEventCreateWithFlags(&evS, cudaEventDisableTiming);
        cudaEventCreateWithFlags(&evT, cudaEventDisableTiming);
        cudaEventCreateWithFlags(&evP, cudaEventDisableTiming);
        cudaEventCreateWithFlags(&ev2, cudaEventDisableTiming);
        inited = 1;
    }

    // fork s1 from the main (capture) stream
    cudaEventRecord(evS, 0);
    cudaStreamWaitEvent(s1, evS, 0);

    // s1: fused weight prep
    prep_weights<<<3072, 256, 0, s1>>>(w_in, w_out, w_off, b_off, w_mask, b_mask);
    cudaEventRecord(evP, s1);

    // s0: NCHW -> NHWC (fp16)
    nchw_to_nhwc<<<dim3(HW / 32, Cc / 32, Bn), dim3(32, 8)>>>(x);
    cudaEventRecord(evT, 0);

    // s1: depthwise branch + offset/mask GEMM (after transpose)
    cudaStreamWaitEvent(s1, evT, 0);
    dw_ln_gelu<<<Mtot / 8, 256, 0, s1>>>(w_dw, b_dw, ln_g, ln_b);
    gemm_om<<<dim3(NPAD / 128, Mtot / 128), 256, HF_DSMEM, s1>>>();
    cudaEventRecord(ev2, s1);

    // s0: input_proj — overlaps with dw+gemm_om on s1
    cudaStreamWaitEvent(0, evP, 0);
    gemm_in<<<dim3(Cc / 128, Mtot / 128), 256, HF_DSMEM>>>(b_in);

    // join: dcn needs xp (s0) + om (s1)
    cudaStreamWaitEvent(0, ev2, 0);
    dcn_sample<<<(Mtot * (Gg / 4)) / 8, 256>>>();
    // output_proj + BN + SiLU (fp16 MMA)
    gemm_out<<<dim3(Cc / 128, Mtot / 128), 256, HF_DSMEM>>>(b_out, bn_g, bn_b,
                                                            bn_m, bn_v, (float*)d_out);
}

// round 17
// speedup vs baseline: 1.9019x; 1.0386x over previous
#include <cuda_runtime.h>
#include <cuda_bf16.h>
#include <cuda_fp16.h>
#include <math.h>
#include <cstdint>

typedef unsigned int u32;
typedef unsigned short u16;
typedef unsigned long long u64;

// Problem constants
#define Bn 4
#define Cc 512
#define Hh 56
#define Ww 56
#define Gg 16
#define Pp 9
#define GC 32
#define HW 3136          // 56*56
#define Mtot 12544       // B*H*W
#define Noff 288         // G*P*2
#define Nmsk 144         // G*P
#define Ncat 432         // Noff+Nmsk
#define NPAD 512         // Ncat padded to 128 multiple

// ---------------- scratch (device globals; no allocation allowed) ----------
__device__ __half g_xa[Mtot * Cc];        // fp16 NHWC (GEMM1 A + depthwise in)
__device__ __half g_xph[Mtot * Cc];       // input_proj output fp16 (dcn only)
__device__ __half g_x1h[Mtot * Cc];       // dw+LN+GELU fp16 (GEMM2 A)
__device__ float  g_om[Mtot * Ncat];      // [offset|mask logits]
__device__ __half g_ysh[Mtot * Cc];       // DCN output fp16 (GEMM3 A)
__device__ __half g_winT[Cc * Cc];        // w_in^T fp16: [n][k]
__device__ __half g_wcatT[NPAD * Cc];     // concat weight^T fp16: [n][k]
__device__ __half g_woutT[Cc * Cc];       // w_out^T fp16: [n][k]
__device__ float  g_bcat[NPAD];

// ---------------- helpers ---------------------------------------------------
__device__ __forceinline__ void ldmA4(u32* r, u32 addr) {
    asm volatile("ldmatrix.sync.aligned.m8n8.x4.shared.b16 {%0,%1,%2,%3}, [%4];\n"
                 : "=r"(r[0]), "=r"(r[1]), "=r"(r[2]), "=r"(r[3]) : "r"(addr));
}
__device__ __forceinline__ void ldmB4(u32* r, u32 addr) {
    asm volatile("ldmatrix.sync.aligned.m8n8.x4.shared.b16 {%0,%1,%2,%3}, [%4];\n"
                 : "=r"(r[0]), "=r"(r[1]), "=r"(r[2]), "=r"(r[3]) : "r"(addr));
}
__device__ __forceinline__ void mma_f16(float* c, const u32* a, const u32* b) {
    asm volatile("mma.sync.aligned.m16n8k16.row.col.f32.f16.f16.f32 "
                 "{%0,%1,%2,%3}, {%4,%5,%6,%7}, {%8,%9}, {%0,%1,%2,%3};\n"
                 : "+f"(c[0]), "+f"(c[1]), "+f"(c[2]), "+f"(c[3])
                 : "r"(a[0]), "r"(a[1]), "r"(a[2]), "r"(a[3]), "r"(b[0]), "r"(b[1]));
}
__device__ __forceinline__ void cpa16(u32 dst, const void* src) {
    asm volatile("cp.async.cg.shared.global [%0], [%1], 16;\n" :: "r"(dst), "l"(src));
}
__device__ __forceinline__ void cpcommit() { asm volatile("cp.async.commit_group;\n"); }
__device__ __forceinline__ void cpwait0() { asm volatile("cp.async.wait_group 0;\n"); }
__device__ __forceinline__ void cpwait1() { asm volatile("cp.async.wait_group 1;\n"); }

// ---------------- fused weight prep (fp16, transposed) -----------------------
__global__ __launch_bounds__(256)
void prep_weights(const float* __restrict__ w_in, const float* __restrict__ w_out,
                  const float* __restrict__ w_off, const float* __restrict__ b_off,
                  const float* __restrict__ w_mask, const float* __restrict__ b_mask) {
    const int seg = blockIdx.x >> 10;
    const int i = ((blockIdx.x & 1023) << 8) + threadIdx.x;
    if (seg == 0) {
        const int k = i >> 9;
        const int n = i & 511;
        g_winT[n * Cc + k] = __float2half_rn(w_in[i]);
    } else if (seg == 1) {
        const int k = i >> 9;
        const int n = i & 511;
        g_woutT[n * Cc + k] = __float2half_rn(w_out[i]);
    } else {
        const int n = i >> 9;
        const int k = i & 511;
        float v = 0.f;
        if (n < Noff) v = w_off[k * Noff + n];
        else if (n < Ncat) v = w_mask[k * Nmsk + (n - Noff)];
        g_wcatT[i] = __float2half_rn(v);
        if (i < NPAD)
            g_bcat[i] = (i < Noff) ? b_off[i] : (i < Ncat ? b_mask[i - Noff] : 0.f);
    }
}

// ---------------- NCHW -> NHWC transpose (fp16, vectorized stores) ----------
__global__ __launch_bounds__(256)
void nchw_to_nhwc(const float* __restrict__ x) {
    __shared__ float tile[32][33];
    const int bb = blockIdx.z;
    const int hw0 = blockIdx.x * 32;
    const int c0 = blockIdx.y * 32;
    const int tx = threadIdx.x;
    const int ty = threadIdx.y;
    const float* xb = x + (size_t)bb * Cc * HW;
    #pragma unroll
    for (int i = 0; i < 32; i += 8)
        tile[ty + i][tx] = xb[(size_t)(c0 + ty + i) * HW + hw0 + tx];
    __syncthreads();
    const int tid = ty * 32 + tx;
    const int sx = tid & 15;     // channel pair index
    const int sy = tid >> 4;     // 0..15 (hw within tile)
    #pragma unroll
    for (int i = 0; i < 32; i += 16) {
        const int hwl = sy + i;
        const __half2 v = __floats2half2_rn(tile[2 * sx][hwl], tile[2 * sx + 1][hwl]);
        *(__half2*)&g_xa[((size_t)bb * HW + hw0 + hwl) * Cc + c0 + 2 * sx] = v;
    }
}

// ================= fp16 GEMM: BM=128 BN=128 BK=64, 3-stage ==================
#define HF_STG 32768
#define HF_DSMEM (3 * HF_STG)

__device__ __forceinline__ void hf_fill(const __half* __restrict__ A,
                                        const __half* __restrict__ B,
                                        int bm, int bn, int kt, u32 stg) {
    const int t = threadIdx.x;
    const int row = t >> 1;
    const int cb = (t & 1) * 4;
    const size_t ka = (size_t)(bm + row) * Cc + kt * 64;
    const size_t kb = (size_t)(bn + row) * Cc + kt * 64;
    #pragma unroll
    for (int i = 0; i < 4; i++) {
        const int c = cb + i;
        const u32 d = (u32)(row * 128 + ((c ^ (row & 7)) << 4));
        cpa16(stg + d,         (const void*)(A + ka + c * 8));
        cpa16(stg + 16384 + d, (const void*)(B + kb + c * 8));
    }
    cpcommit();
}

__device__ __forceinline__ void hf_compute(u32 stg, int wm, int wn, int lane,
                                           float acc[4][4][4]) {
    const u32 stgB = stg + 16384;
    const int arow7 = lane & 7;
    const int arow8 = ((lane >> 3) & 1) * 8;
    const int achk = lane >> 4;
    const int brow8 = (lane >> 4) * 8;
    const int bchk = (lane >> 3) & 1;
    #pragma unroll
    for (int ks = 0; ks < 4; ks++) {
        u32 a[4][4];
        #pragma unroll
        for (int mf = 0; mf < 4; mf++) {
            const int row = wm + mf * 16 + arow7 + arow8;
            const int ch = 2 * ks + achk;
            ldmA4(a[mf], stg + (u32)(row * 128 + ((ch ^ (row & 7)) << 4)));
        }
        u32 b4[2][4];
        #pragma unroll
        for (int j = 0; j < 2; j++) {
            const int row = wn + (2 * j) * 8 + brow8 + arow7;
            const int ch = 2 * ks + bchk;
            ldmB4(b4[j], stgB + (u32)(row * 128 + ((ch ^ (row & 7)) << 4)));
        }
        #pragma unroll
        for (int mf = 0; mf < 4; mf++) {
            #pragma unroll
            for (int j = 0; j < 2; j++) {
                mma_f16(acc[mf][2 * j + 0], a[mf], &b4[j][0]);
                mma_f16(acc[mf][2 * j + 1], a[mf], &b4[j][2]);
            }
        }
    }
}

__device__ __forceinline__ void hf_core(const __half* __restrict__ A,
                                        const __half* __restrict__ B,
                                        int bm, int bn, u32 smbase,
                                        float acc[4][4][4]) {
    const int wid = threadIdx.x >> 5;
    const int lane = threadIdx.x & 31;
    const int wm = (wid & 1) * 64;
    const int wn = (wid >> 1) * 32;
    const u32 st[3] = {smbase, smbase + HF_STG, smbase + 2 * HF_STG};
    hf_fill(A, B, bm, bn, 0, st[0]);
    hf_fill(A, B, bm, bn, 1, st[1]);
    #pragma unroll 1
    for (int kt = 0; kt < 8; kt++) {
        if (kt == 7) cpwait0(); else cpwait1();
        __syncthreads();
        if (kt + 2 < 8) {
            int s2 = kt + 2; s2 -= (s2 / 3) * 3;
            hf_fill(A, B, bm, bn, kt + 2, st[s2]);
        }
        int s = kt; s -= (s / 3) * 3;
        hf_compute(st[s], wm, wn, lane, acc);
    }
}

// ---- GEMM 1 (fp16): xp(fp16) = xa @ winT^T + b_in --------------------------
__global__ __launch_bounds__(256, 2)
void gemm_in(const float* __restrict__ bias) {
    extern __shared__ char smem[];
    const u32 smbase = (u32)__cvta_generic_to_shared(smem);
    float acc[4][4][4];
    #pragma unroll
    for (int i = 0; i < 4; i++)
        #pragma unroll
        for (int j = 0; j < 4; j++)
            #pragma unroll
            for (int q = 0; q < 4; q++) acc[i][j][q] = 0.f;
    const int bm = blockIdx.y * 128;
    const int bn = blockIdx.x * 128;
    hf_core(g_xa, g_winT, bm, bn, smbase, acc);

    const int wid = threadIdx.x >> 5;
    const int lane = threadIdx.x & 31;
    const int wm = (wid & 1) * 64;
    const int wn = (wid >> 1) * 32;
    const int r0 = lane >> 2;
    const int c0 = (lane & 3) * 2;
    #pragma unroll
    for (int mf = 0; mf < 4; mf++) {
        #pragma unroll
        for (int nf = 0; nf < 4; nf++) {
            const int col = bn + wn + nf * 8 + c0;
            #pragma unroll
            for (int half = 0; half < 2; half++) {
                const int row = bm + wm + mf * 16 + r0 + half * 8;
                const float y0 = acc[mf][nf][half * 2 + 0] + bias[col];
                const float y1 = acc[mf][nf][half * 2 + 1] + bias[col + 1];
                *(__half2*)&g_xph[(size_t)row * Cc + col] = __floats2half2_rn(y0, y1);
            }
        }
    }
}

// ---- GEMM 2 (fp16): g_om = x1 @ wcatT^T + bcat  (N=512 pad, store 432) -----
__global__ __launch_bounds__(256, 2)
void gemm_om() {
    extern __shared__ char smem[];
    const u32 smbase = (u32)__cvta_generic_to_shared(smem);
    float acc[4][4][4];
    #pragma unroll
    for (int i = 0; i < 4; i++)
        #pragma unroll
        for (int j = 0; j < 4; j++)
            #pragma unroll
            for (int q = 0; q < 4; q++) acc[i][j][q] = 0.f;
    const int bm = blockIdx.y * 128;
    const int bn = blockIdx.x * 128;
    hf_core(g_x1h, g_wcatT, bm, bn, smbase, acc);

    const int wid = threadIdx.x >> 5;
    const int lane = threadIdx.x & 31;
    const int wm = (wid & 1) * 64;
    const int wn = (wid >> 1) * 32;
    const int r0 = lane >> 2;
    const int c0 = (lane & 3) * 2;
    #pragma unroll
    for (int mf = 0; mf < 4; mf++) {
        #pragma unroll
        for (int nf = 0; nf < 4; nf++) {
            const int col = bn + wn + nf * 8 + c0;
            if (col < Ncat) {
                #pragma unroll
                for (int half = 0; half < 2; half++) {
                    const int row = bm + wm + mf * 16 + r0 + half * 8;
                    float2 v;
                    v.x = acc[mf][nf][half * 2 + 0] + g_bcat[col];
                    v.y = acc[mf][nf][half * 2 + 1] + g_bcat[col + 1];
                    *(float2*)&g_om[(size_t)row * Ncat + col] = v;
                }
            }
        }
    }
}

// ---- GEMM 3 (fp16): out = SiLU(BN(ys @ woutT^T + b_out)) in NCHW -----------
__global__ __launch_bounds__(256, 2)
void gemm_out(const float* __restrict__ bias,
              const float* __restrict__ bn_g, const float* __restrict__ bn_b,
              const float* __restrict__ bn_m, const float* __restrict__ bn_v,
              float* __restrict__ out) {
    extern __shared__ char smem[];
    const u32 smbase = (u32)__cvta_generic_to_shared(smem);
    float acc[4][4][4];
    #pragma unroll
    for (int i = 0; i < 4; i++)
        #pragma unroll
        for (int j = 0; j < 4; j++)
            #pragma unroll
            for (int q = 0; q < 4; q++) acc[i][j][q] = 0.f;
    const int bm = blockIdx.y * 128;
    const int bn = blockIdx.x * 128;
    hf_core(g_ysh, g_woutT, bm, bn, smbase, acc);

    const int wid = threadIdx.x >> 5;
    const int lane = threadIdx.x & 31;
    const int wm = (wid & 1) * 64;
    const int wn = (wid >> 1) * 32;
    const int r0 = lane >> 2;
    const int c0 = (lane & 3) * 2;
    #pragma unroll
    for (int mf = 0; mf < 4; mf++) {
        #pragma unroll
        for (int nf = 0; nf < 4; nf++) {
            const int col = bn + wn + nf * 8 + c0;
            const float s0 = bn_g[col] * rsqrtf(bn_v[col] + 1e-5f);
            const float s1 = bn_g[col + 1] * rsqrtf(bn_v[col + 1] + 1e-5f);
            #pragma unroll
            for (int half = 0; half < 2; half++) {
                const int row = bm + wm + mf * 16 + r0 + half * 8;
                const int bidx = row / HW;
                const int hw = row - bidx * HW;
                float y0 = acc[mf][nf][half * 2 + 0] + bias[col];
                float y1 = acc[mf][nf][half * 2 + 1] + bias[col + 1];
                y0 = (y0 - bn_m[col]) * s0 + bn_b[col];
                y1 = (y1 - bn_m[col + 1]) * s1 + bn_b[col + 1];
                out[((size_t)bidx * Cc + col) * HW + hw]     = y0 / (1.0f + expf(-y0));
                out[((size_t)bidx * Cc + col + 1) * HW + hw] = y1 / (1.0f + expf(-y1));
            }
        }
    }
}

// ------- depthwise 3x3 + LN + GELU: 8-pixel sliding window, fp16 in --------
__global__ __launch_bounds__(256)
void dw_ln_gelu(const float* __restrict__ wdw, const float* __restrict__ bdw,
                const float* __restrict__ lng, const float* __restrict__ lnb) {
    __shared__ float sA[8][8];
    __shared__ float sB[8][8];
    const int m0 = blockIdx.x * 8;
    const int b = m0 / HW;
    const int hw0 = m0 - b * HW;
    const int h = hw0 / Ww;
    const int w0 = hw0 - h * Ww;
    const int tid = threadIdx.x;
    const int wid = tid >> 5;
    const int lane = tid & 31;
    const int c = tid * 2;

    float a0[8], a1[8];
    #pragma unroll
    for (int i = 0; i < 8; i++) { a0[i] = 0.f; a1[i] = 0.f; }

    #pragma unroll
    for (int ky = 0; ky < 3; ky++) {
        const int hy = h + ky - 1;
        if ((unsigned)hy >= (unsigned)Hh) continue;
        const float2 wv0 = *(const float2*)&wdw[(ky * 3 + 0) * Cc + c];
        const float2 wv1 = *(const float2*)&wdw[(ky * 3 + 1) * Cc + c];
        const float2 wv2 = *(const float2*)&wdw[(ky * 3 + 2) * Cc + c];
        float2 rv[10];
        #pragma unroll
        for (int j = 0; j < 10; j++) {
            const int wx = w0 + j - 1;
            if ((unsigned)wx < (unsigned)Ww)
                rv[j] = __half22float2(
                    *(const __half2*)&g_xa[((size_t)(b * HW + hy * Ww + wx)) * Cc + c]);
            else
                rv[j] = make_float2(0.f, 0.f);
        }
        #pragma unroll
        for (int px = 0; px < 8; px++) {
            a0[px] = fmaf(rv[px].x,     wv0.x, a0[px]);
            a1[px] = fmaf(rv[px].y,     wv0.y, a1[px]);
            a0[px] = fmaf(rv[px + 1].x, wv1.x, a0[px]);
            a1[px] = fmaf(rv[px + 1].y, wv1.y, a1[px]);
            a0[px] = fmaf(rv[px + 2].x, wv2.x, a0[px]);
            a1[px] = fmaf(rv[px + 2].y, wv2.y, a1[px]);
        }
    }
    const float2 bb2 = *(const float2*)&bdw[c];
    #pragma unroll
    for (int px = 0; px < 8; px++) { a0[px] += bb2.x; a1[px] += bb2.y; }

    #pragma unroll
    for (int px = 0; px < 8; px++) {
        float part = a0[px] + a1[px];
        #pragma unroll
        for (int s = 16; s > 0; s >>= 1) part += __shfl_xor_sync(0xffffffffu, part, s);
        if (lane == 0) sA[wid][px] = part;
    }
    __syncthreads();
    float mu[8];
    #pragma unroll
    for (int px = 0; px < 8; px++) {
        float s = 0.f;
        #pragma unroll
        for (int i = 0; i < 8; i++) s += sA[i][px];
        mu[px] = s * (1.0f / 512.0f);
    }
    #pragma unroll
    for (int px = 0; px < 8; px++) {
        const float d0 = a0[px] - mu[px];
        const float d1 = a1[px] - mu[px];
        float vp = d0 * d0 + d1 * d1;
        #pragma unroll
        for (int s = 16; s > 0; s >>= 1) vp += __shfl_xor_sync(0xffffffffu, vp, s);
        if (lane == 0) sB[wid][px] = vp;
    }
    __syncthreads();

    const float2 gg = *(const float2*)&lng[c];
    const float2 be = *(const float2*)&lnb[c];
    #pragma unroll
    for (int px = 0; px < 8; px++) {
        float var = 0.f;
        #pragma unroll
        for (int i = 0; i < 8; i++) var += sB[i][px];
        var *= (1.0f / 512.0f);
        const float rstd = rsqrtf(var + 1e-6f);
        float o0 = (a0[px] - mu[px]) * rstd * gg.x + be.x;
        float o1 = (a1[px] - mu[px]) * rstd * gg.y + be.y;
        o0 = 0.5f * o0 * (1.0f + erff(o0 * 0.7071067811865475f));
        o1 = 0.5f * o1 * (1.0f + erff(o1 * 0.7071067811865475f));
        *(__half2*)&g_x1h[(size_t)(m0 + px) * Cc + c] = __floats2half2_rn(o0, o1);
    }
}

// ------- DCNv3 sampling + fused softmax: warp = (pixel, group-octet) -------
// 4 lanes per group (8 groups/warp, 2 warps/pixel); each lane handles 8 ch.
__global__ __launch_bounds__(256)
void dcn_sample() {
    const int wuid = blockIdx.x * 8 + (threadIdx.x >> 5);
    const int lane = threadIdx.x & 31;
    if (wuid >= Mtot * 2) return;
    const int m = wuid >> 1;
    const int gh = wuid & 1;                 // group half: 0 -> g 0-7, 1 -> g 8-15
    const int g = gh * 8 + (lane >> 2);
    const int ch = (lane & 3) * 8;
    const int b = m / HW;
    const int hw = m - b * HW;
    const int h = hw / Ww;
    const int w = hw - h * Ww;

    const float* offp = g_om + (size_t)m * Ncat + g * (Pp * 2);
    const float* mskp = g_om + (size_t)m * Ncat + Noff + g * Pp;
    const __half* base = g_xph + (size_t)b * HW * Cc + g * GC + ch;

    float logit[Pp];
    float mx = -1e30f;
    #pragma unroll
    for (int p = 0; p < Pp; p++) { logit[p] = mskp[p]; mx = fmaxf(mx, logit[p]); }
    float ssum = 0.f;
    #pragma unroll
    for (int p = 0; p < Pp; p++) { logit[p] = __expf(logit[p] - mx); ssum += logit[p]; }
    const float sinv = 1.0f / ssum;

    float acc[8];
    #pragma unroll
    for (int i = 0; i < 8; i++) acc[i] = 0.f;

    #pragma unroll
    for (int p = 0; p < Pp; p++) {
        const int kx = p / 3;
        const int ky = p - kx * 3;
        const float2 o2 = *(const float2*)&offp[2 * p];
        const float fx = (float)(w + kx - 1) + o2.x;
        const float fy = (float)(h + ky - 1) + o2.y;
        const float x0f = floorf(fx);
        const float y0f = floorf(fy);
        const float txf = fx - x0f;
        const float tyf = fy - y0f;
        const int x0 = (int)x0f;
        const int y0 = (int)y0f;
        const float msk = logit[p] * sinv;
        const float w00 = (1.f - tyf) * (1.f - txf) * msk;
        const float w01 = (1.f - tyf) * txf * msk;
        const float w10 = tyf * (1.f - txf) * msk;
        const float w11 = tyf * txf * msk;
        const bool yi0 = (unsigned)y0 < (unsigned)Hh;
        const bool yi1 = (unsigned)(y0 + 1) < (unsigned)Hh;
        const bool xi0 = (unsigned)x0 < (unsigned)Ww;
        const bool xi1 = (unsigned)(x0 + 1) < (unsigned)Ww;
        #pragma unroll
        for (int cy = 0; cy < 2; cy++) {
            #pragma unroll
            for (int cx = 0; cx < 2; cx++) {
                const bool ok = (cy ? yi1 : yi0) && (cx ? xi1 : xi0);
                if (ok) {
                    const float wgt = cy ? (cx ? w11 : w10) : (cx ? w01 : w00);
                    const uint4 q = *(const uint4*)&base[(size_t)((y0 + cy) * Ww + x0 + cx) * Cc];
                    const float2 f0 = __half22float2(*(const __half2*)&q.x);
                    const float2 f1 = __half22float2(*(const __half2*)&q.y);
                    const float2 f2 = __half22float2(*(const __half2*)&q.z);
                    const float2 f3 = __half22float2(*(const __half2*)&q.w);
                    acc[0] = fmaf(wgt, f0.x, acc[0]);
                    acc[1] = fmaf(wgt, f0.y, acc[1]);
                    acc[2] = fmaf(wgt, f1.x, acc[2]);
                    acc[3] = fmaf(wgt, f1.y, acc[3]);
                    acc[4] = fmaf(wgt, f2.x, acc[4]);
                    acc[5] = fmaf(wgt, f2.y, acc[5]);
                    acc[6] = fmaf(wgt, f3.x, acc[6]);
                    acc[7] = fmaf(wgt, f3.y, acc[7]);
                }
            }
        }
    }
    const __half2 h0 = __floats2half2_rn(acc[0], acc[1]);
    const __half2 h1 = __floats2half2_rn(acc[2], acc[3]);
    const __half2 h2 = __floats2half2_rn(acc[4], acc[5]);
    const __half2 h3 = __floats2half2_rn(acc[6], acc[7]);
    uint4 o;
    o.x = *(const u32*)&h0; o.y = *(const u32*)&h1;
    o.z = *(const u32*)&h2; o.w = *(const u32*)&h3;
    *(uint4*)&g_ysh[(size_t)m * Cc + g * GC + ch] = o;
}

// ---------------- host launch ----------------------------------------------
extern "C" void kernel_launch(void* const* d_in, const int* in_sizes, int n_in,
                              void* d_out, int out_size) {
    const float* x      = (const float*)d_in[0];
    const float* w_in   = (const float*)d_in[1];
    const float* b_in   = (const float*)d_in[2];
    const float* w_dw   = (const float*)d_in[3];
    const float* b_dw   = (const float*)d_in[4];
    const float* ln_g   = (const float*)d_in[5];
    const float* ln_b   = (const float*)d_in[6];
    const float* w_off  = (const float*)d_in[7];
    const float* b_off  = (const float*)d_in[8];
    const float* w_mask = (const float*)d_in[9];
    const float* b_mask = (const float*)d_in[10];
    const float* w_out  = (const float*)d_in[11];
    const float* b_out  = (const float*)d_in[12];
    const float* bn_g   = (const float*)d_in[13];
    const float* bn_b   = (const float*)d_in[14];
    const float* bn_m   = (const float*)d_in[15];
    const float* bn_v   = (const float*)d_in[16];

    // one-time setup (first call is the uncaptured correctness run)
    static int inited = 0;
    static cudaStream_t s1;
    static cudaEvent_t evS, evT, evP, ev2;
    if (!inited) {
        cudaFuncSetAttribute(gemm_in, cudaFuncAttributeMaxDynamicSharedMemorySize, HF_DSMEM);
        cudaFuncSetAttribute(gemm_om, cudaFuncAttributeMaxDynamicSharedMemorySize, HF_DSMEM);
        cudaFuncSetAttribute(gemm_out, cudaFuncAttributeMaxDynamicSharedMemorySize, HF_DSMEM);
        cudaStreamCreateWithFlags(&s1, cudaStreamNonBlocking);
        cudaEventCreateWithFlags(&evS, cudaEventDisableTiming);
        cudaEventCreateWithFlags(&evT, cudaEventDisableTiming);
        cudaEventCreateWithFlags(&evP, cudaEventDisableTiming);
        cudaEventCreateWithFlags(&ev2, cudaEventDisableTiming);
        inited = 1;
    }

    // fork s1 from the main (capture) stream
    cudaEventRecord(evS, 0);
    cudaStreamWaitEvent(s1, evS, 0);

    // s1: fused weight prep
    prep_weights<<<3072, 256, 0, s1>>>(w_in, w_out, w_off, b_off, w_mask, b_mask);
    cudaEventRecord(evP, s1);

    // s0: NCHW -> NHWC (fp16)
    nchw_to_nhwc<<<dim3(HW / 32, Cc / 32, Bn), dim3(32, 8)>>>(x);
    cudaEventRecord(evT, 0);

    // s1: depthwise branch + offset/mask GEMM (after transpose)
    cudaStreamWaitEvent(s1, evT, 0);
    dw_ln_gelu<<<Mtot / 8, 256, 0, s1>>>(w_dw, b_dw, ln_g, ln_b);
    gemm_om<<<dim3(NPAD / 128, Mtot / 128), 256, HF_DSMEM, s1>>>();
    cudaEventRecord(ev2, s1);

    // s0: input_proj — overlaps with dw+gemm_om on s1
    cudaStreamWaitEvent(0, evP, 0);
    gemm_in<<<dim3(Cc / 128, Mtot / 128), 256, HF_DSMEM>>>(b_in);

    // join: dcn needs xp (s0) + om (s1)
    cudaStreamWaitEvent(0, ev2, 0);
    dcn_sample<<<(Mtot * 2) / 8, 256>>>();
    // output_proj + BN + SiLU (fp16 MMA)
    gemm_out<<<dim3(Cc / 128, Mtot / 128), 256, HF_DSMEM>>>(b_out, bn_g, bn_b,
                                                            bn_m, bn_v, (float*)d_out);
}